// round 11
// baseline (speedup 1.0000x reference)
#include <cuda_runtime.h>
#include <cuda_fp16.h>
#include <math.h>
#include <stdint.h>

#define Bsz 64
#define Nn  1029
#define Dd  768
#define Hh  12
#define dh  64
#define Kk  128
#define Rr  5
#define Mm  4
#define Pp  1024          // N - R
#define CTX 133           // R + K
#define NCH 4             // attention/out pipeline chunks
#define BCH (Bsz / NCH)   // 16 batches per chunk

// ---------------- scratch (static device globals: allocation-free) ----------
__device__ int    g_idx[Bsz];
__device__ __half g_xh[(size_t)Bsz * Nn * Dd];
__device__ __half g_wqT[Dd * Dd];
__device__ __half g_wctxT[2 * Dd * Dd];
__device__ __half g_woutT[Dd * Dd];
__device__ __half g_qctx[(size_t)Bsz * Kk * Dd];
__device__ __half g_probs[(size_t)Bsz * Kk * Pp];
__device__ __half g_ctx[(size_t)Bsz * CTX * Dd];
__device__ __half g_kv[(size_t)Bsz * CTX * 2 * Dd];
__device__ __half g_q[(size_t)Bsz * Nn * Dd];
__device__ __half g_y[(size_t)Bsz * Nn * Dd];

// ---------------- helpers ----------------------------------------------------
__device__ __forceinline__ uint32_t pk2(float a, float b) {
    __half2 h = __floats2half2_rn(a, b);
    return *reinterpret_cast<uint32_t*>(&h);
}

__device__ __forceinline__ void mma_f16(float* c, const uint32_t* a, const uint32_t* b) {
    asm volatile(
        "mma.sync.aligned.m16n8k16.row.col.f32.f16.f16.f32 "
        "{%0,%1,%2,%3}, {%4,%5,%6,%7}, {%8,%9}, {%0,%1,%2,%3};\n"
        : "+f"(c[0]), "+f"(c[1]), "+f"(c[2]), "+f"(c[3])
        : "r"(a[0]), "r"(a[1]), "r"(a[2]), "r"(a[3]), "r"(b[0]), "r"(b[1]));
}

__device__ __forceinline__ void ldsm4(uint32_t& r0, uint32_t& r1, uint32_t& r2,
                                      uint32_t& r3, uint32_t a) {
    asm volatile("ldmatrix.sync.aligned.m8n8.x4.shared.b16 {%0,%1,%2,%3}, [%4];"
                 : "=r"(r0), "=r"(r1), "=r"(r2), "=r"(r3) : "r"(a));
}
__device__ __forceinline__ void ldsm4t(uint32_t& r0, uint32_t& r1, uint32_t& r2,
                                       uint32_t& r3, uint32_t a) {
    asm volatile("ldmatrix.sync.aligned.m8n8.x4.trans.shared.b16 {%0,%1,%2,%3}, [%4];"
                 : "=r"(r0), "=r"(r1), "=r"(r2), "=r"(r3) : "r"(a));
}

__device__ __forceinline__ void cp16(void* smem_dst, const void* gsrc, unsigned bytes) {
    unsigned saddr = (unsigned)__cvta_generic_to_shared(smem_dst);
    asm volatile("cp.async.cg.shared.global [%0], [%1], 16, %2;\n"
                 :: "r"(saddr), "l"(gsrc), "r"(bytes));
}
__device__ __forceinline__ void cp_commit() { asm volatile("cp.async.commit_group;\n"); }
template<int N> __device__ __forceinline__ void cp_wait() {
    asm volatile("cp.async.wait_group %0;\n" :: "n"(N));
}

// ---------------- conversion kernels ------------------------------------------
__global__ void f2h_kernel(const float4* __restrict__ src, uint2* __restrict__ dst, int n4)
{
    int i = blockIdx.x * blockDim.x + threadIdx.x;
    if (i < n4) {
        float4 v = src[i];
        uint2 o;
        o.x = pk2(v.x, v.y);
        o.y = pk2(v.z, v.w);
        dst[i] = o;
    }
}

__global__ void transpose_h(const float* __restrict__ src, __half* __restrict__ dst,
                            int K, int N)
{
    __shared__ float t[32][33];
    int k0 = blockIdx.y * 32, n0 = blockIdx.x * 32;
    int tx = threadIdx.x, ty = threadIdx.y;   // 32 x 8
    for (int i = ty; i < 32; i += 8)
        t[i][tx] = src[(size_t)(k0 + i) * N + n0 + tx];
    __syncthreads();
    for (int i = ty; i < 32; i += 8)
        dst[(size_t)(n0 + i) * K + k0 + tx] = __float2half_rn(t[tx][i]);
}

// ---------------- cls_n, sims, argmax (fp32 exact) ---------------------------
__global__ void cls_kernel(const float* __restrict__ x,
                           const float* __restrict__ cent,
                           float* __restrict__ cls_out,
                           float* __restrict__ idx_out)
{
    int b = blockIdx.x;
    int tid = threadIdx.x;
    __shared__ float xs[Dd];
    __shared__ float red[256];
    __shared__ float sims[Mm];
    __shared__ float inv_s;

    float ss = 0.f;
    for (int i = tid; i < Dd; i += 256) {
        float v = x[(size_t)b * Nn * Dd + i];
        xs[i] = v;
        ss += v * v;
    }
    red[tid] = ss; __syncthreads();
    for (int s = 128; s > 0; s >>= 1) { if (tid < s) red[tid] += red[tid + s]; __syncthreads(); }
    if (tid == 0) inv_s = 1.f / fmaxf(sqrtf(red[0]), 1e-12f);
    __syncthreads();
    float inv = inv_s;

    for (int m = 0; m < Mm; m++) {
        float p = 0.f;
        for (int i = tid; i < Dd; i += 256) p += xs[i] * cent[m * Dd + i];
        red[tid] = p; __syncthreads();
        for (int s = 128; s > 0; s >>= 1) { if (tid < s) red[tid] += red[tid + s]; __syncthreads(); }
        if (tid == 0) sims[m] = red[0] * inv;
        __syncthreads();
    }
    if (tid == 0) {
        int best = 0; float bv = sims[0];
        for (int m = 1; m < Mm; m++) if (sims[m] > bv) { bv = sims[m]; best = m; }
        g_idx[b] = best;
        if (idx_out) idx_out[b] = (float)best;
    }
    if (cls_out)
        for (int i = tid; i < Dd; i += 256)
            cls_out[(size_t)b * Dd + i] = xs[i] * inv;
}

// ---------------- gather Q_banks[idx] (half, 2-D grid, float4) ---------------
__global__ void gather_qctx_kernel(const float* __restrict__ Qb)
{
    int b = blockIdx.y;
    int i4 = blockIdx.x * blockDim.x + threadIdx.x;      // float4 index within bank
    const int n4 = Kk * Dd / 4;                          // 24576
    if (i4 < n4) {
        const float4 v = reinterpret_cast<const float4*>(
            Qb + (size_t)g_idx[b] * Kk * Dd)[i4];
        uint2 o;
        o.x = pk2(v.x, v.y);
        o.y = pk2(v.z, v.w);
        reinterpret_cast<uint2*>(g_qctx + (size_t)b * Kk * Dd)[i4] = o;
    }
}

__global__ void xreg_kernel()
{
    int i = blockIdx.x * blockDim.x + threadIdx.x;       // u32 units
    const int total = Bsz * Rr * Dd / 2;
    if (i < total) {
        int b = i / (Rr * Dd / 2);
        int r = i - b * (Rr * Dd / 2);
        reinterpret_cast<uint32_t*>(g_ctx)[(size_t)b * CTX * Dd / 2 + r] =
            reinterpret_cast<const uint32_t*>(g_xh)[(size_t)b * Nn * Dd / 2 + r];
    }
}

// ---------------- fp16 tensor-core GEMM, 4-stage cp.async + ldmatrix --------
template<bool TRANSB, bool BIAS, bool OUTHALF>
__global__ __launch_bounds__(256, 2)
void hgemm(const __half* __restrict__ A, const __half* __restrict__ Bm,
           const float* __restrict__ bias, void* __restrict__ Cv,
           int M, int N, int Kd, int lda, int ldb, int ldc,
           long long sA, long long sB, long long sC)
{
    extern __shared__ uint32_t smu[];
    const int ASTG = 128 * 20;
    const int BSTG = TRANSB ? 128 * 20 : 32 * 68;
    uint32_t* smA = smu;
    uint32_t* smB = smu + 4 * ASTG;
    const uint32_t sbA = (uint32_t)__cvta_generic_to_shared(smA);
    const uint32_t sbB = (uint32_t)__cvta_generic_to_shared(smB);

    const __half* Ab = A  + (long long)blockIdx.z * sA;
    const __half* Bb = Bm + (long long)blockIdx.z * sB;

    const int row0 = blockIdx.y * 128;
    const int col0 = blockIdx.x * 128;
    const int tid  = threadIdx.x;
    const int lane = tid & 31;
    const int warp = tid >> 5;
    const int wm = warp >> 1;
    const int wn = warp & 1;
    const int g   = lane >> 2;
    const int tig = lane & 3;

    const int lrow = ((lane >> 3) & 1) * 8 + (lane & 7);
    const int lk8  = (lane >> 4) * 8;
    uint32_t aoff[2], boff[4];
#pragma unroll
    for (int im = 0; im < 2; im++)
        aoff[im] = (uint32_t)(((wm * 32 + im * 16 + lrow) * 40 + lk8) * 2);
#pragma unroll
    for (int p = 0; p < 4; p++) {
        if (TRANSB)
            boff[p] = (uint32_t)(((wn * 64 + p * 16 + lrow) * 40 + lk8) * 2);
        else
            boff[p] = (uint32_t)(((((lane >> 4) & 1) * 8 + (lane & 7)) * 136
                                  + wn * 64 + p * 16 + ((lane >> 3) & 1) * 8) * 2);
    }

    float acc[2][8][4];
#pragma unroll
    for (int im = 0; im < 2; im++)
#pragma unroll
        for (int in = 0; in < 8; in++)
#pragma unroll
            for (int j = 0; j < 4; j++) acc[im][in][j] = 0.f;

    auto loadA = [&](int stg, int k0) {
        uint32_t* dst = smA + stg * ASTG;
#pragma unroll
        for (int it = 0; it < 2; it++) {
            int id = tid + it * 256;
            int r  = id >> 2;
            int c  = (id & 3) * 4;
            int gr = row0 + r;
            unsigned ok = (gr < M) ? 16u : 0u;
            const __half* src = Ab + (size_t)(gr < M ? gr : 0) * lda + k0 + c * 2;
            cp16(dst + r * 20 + c, src, ok);
        }
    };
    auto loadB = [&](int stg, int k0) {
        uint32_t* dst = smB + stg * BSTG;
#pragma unroll
        for (int it = 0; it < 2; it++) {
            int id = tid + it * 256;
            if (TRANSB) {
                int n = id >> 2;
                int c = (id & 3) * 4;
                cp16(dst + n * 20 + c, Bb + (size_t)(col0 + n) * ldb + k0 + c * 2, 16u);
            } else {
                int kr = id >> 4;
                int ch = id & 15;
                cp16(dst + kr * 68 + ch * 4, Bb + (size_t)(k0 + kr) * ldb + col0 + ch * 8, 16u);
            }
        }
    };

    loadA(0, 0);  loadB(0, 0);  cp_commit();
    loadA(1, 32); loadB(1, 32); cp_commit();
    loadA(2, 64); loadB(2, 64); cp_commit();

    const int nk = Kd >> 5;
    for (int i = 0; i < nk; i++) {
        int rem = nk - 1 - i;
        if (rem >= 2)      cp_wait<2>();
        else if (rem == 1) cp_wait<1>();
        else               cp_wait<0>();
        __syncthreads();
        if (i + 3 < nk) {
            int s4 = (i + 3) & 3;
            loadA(s4, (i + 3) * 32);
            loadB(s4, (i + 3) * 32);
            cp_commit();
        }

        const uint32_t baA = sbA + (uint32_t)((i & 3) * ASTG * 4);
        const uint32_t baB = sbB + (uint32_t)((i & 3) * BSTG * 4);

#pragma unroll
        for (int s = 0; s < 2; s++) {
            uint32_t afr[2][4], bfr[8][2];
#pragma unroll
            for (int im = 0; im < 2; im++)
                ldsm4(afr[im][0], afr[im][1], afr[im][2], afr[im][3],
                      baA + aoff[im] + s * 32);
#pragma unroll
            for (int p = 0; p < 4; p++) {
                if (TRANSB)
                    ldsm4(bfr[2 * p][0], bfr[2 * p + 1][0], bfr[2 * p][1], bfr[2 * p + 1][1],
                          baB + boff[p] + s * 32);
                else
                    ldsm4t(bfr[2 * p][0], bfr[2 * p + 1][0], bfr[2 * p][1], bfr[2 * p + 1][1],
                           baB + boff[p] + s * 4352);
            }
#pragma unroll
            for (int im = 0; im < 2; im++)
#pragma unroll
                for (int in = 0; in < 8; in++)
                    mma_f16(acc[im][in], afr[im], bfr[in]);
        }
        // trailing barrier elided: next iteration's leading barrier protects the ring
    }

#pragma unroll
    for (int im = 0; im < 2; im++) {
        int rb = row0 + wm * 32 + im * 16 + g;
#pragma unroll
        for (int in = 0; in < 8; in++) {
            int cb = col0 + wn * 64 + in * 8 + 2 * tig;
            float b0 = BIAS ? bias[cb] : 0.f;
            float b1 = BIAS ? bias[cb + 1] : 0.f;
            float v0 = acc[im][in][0] + b0, v1 = acc[im][in][1] + b1;
            float v2 = acc[im][in][2] + b0, v3 = acc[im][in][3] + b1;
            if (OUTHALF) {
                __half* C = (__half*)Cv + (long long)blockIdx.z * sC;
                if (rb < M)
                    *reinterpret_cast<uint32_t*>(&C[(size_t)rb * ldc + cb]) = pk2(v0, v1);
                if (rb + 8 < M)
                    *reinterpret_cast<uint32_t*>(&C[(size_t)(rb + 8) * ldc + cb]) = pk2(v2, v3);
            } else {
                float* C = (float*)Cv + (long long)blockIdx.z * sC;
                if (rb < M)
                    *reinterpret_cast<float2*>(&C[(size_t)rb * ldc + cb]) = make_float2(v0, v1);
                if (rb + 8 < M)
                    *reinterpret_cast<float2*>(&C[(size_t)(rb + 8) * ldc + cb]) = make_float2(v2, v3);
            }
        }
    }
}

// ---------------- row softmax over P=1024: half in-place ----------------------
__global__ void softmax_kernel(__half* __restrict__ pr)
{
    int row = blockIdx.x;
    uint2* p2 = reinterpret_cast<uint2*>(pr + (size_t)row * Pp);
    int tid = threadIdx.x;
    __shared__ float red[256];

    uint2 u = p2[tid];
    __half2 h0 = *reinterpret_cast<__half2*>(&u.x);
    __half2 h1 = *reinterpret_cast<__half2*>(&u.y);
    float vx = __low2float(h0), vy = __high2float(h0);
    float vz = __low2float(h1), vw = __high2float(h1);

    float mx = fmaxf(fmaxf(vx, vy), fmaxf(vz, vw));
    red[tid] = mx; __syncthreads();
    for (int st = 128; st > 0; st >>= 1) { if (tid < st) red[tid] = fmaxf(red[tid], red[tid + st]); __syncthreads(); }
    mx = red[0]; __syncthreads();

    vx = __expf(vx - mx); vy = __expf(vy - mx);
    vz = __expf(vz - mx); vw = __expf(vw - mx);
    float sm = vx + vy + vz + vw;
    red[tid] = sm; __syncthreads();
    for (int st = 128; st > 0; st >>= 1) { if (tid < st) red[tid] += red[tid + st]; __syncthreads(); }
    float inv = 1.f / red[0];
    uint2 o;
    o.x = pk2(vx * inv, vy * inv);
    o.y = pk2(vz * inv, vw * inv);
    p2[tid] = o;
}

// ---------------- fp16 tensor-core fused attention ----------------------------
// grid (17, BCH*Hh) per chunk, 128 threads (4 warps x 16 query rows).
// b0 = batch offset of this chunk. Keys padded to 144.
__global__ __launch_bounds__(128, 3)
void attn_mma(__half* __restrict__ y, int b0)
{
    extern __shared__ uint32_t smu[];
    uint32_t* Qs = smu;                    // [64][36] u32  (72-half pitch)
    uint32_t* Ks = smu + 64 * 36;          // [144][36]
    uint32_t* Vs = Ks + 144 * 36;          // [144][36]
    uint32_t* Ps = Vs + 144 * 36;          // [64][76] u32  (152-half pitch)
    const uint32_t sQ = (uint32_t)__cvta_generic_to_shared(Qs);
    const uint32_t sK = (uint32_t)__cvta_generic_to_shared(Ks);
    const uint32_t sV = (uint32_t)__cvta_generic_to_shared(Vs);
    const uint32_t sP = (uint32_t)__cvta_generic_to_shared(Ps);

    const int bh = blockIdx.y;
    const int b = b0 + bh / Hh, h = bh % Hh;
    const int n0 = blockIdx.x * 64;
    const int tid = threadIdx.x;
    const int lane = tid & 31;
    const int w = tid >> 5;                // 0..3
    const int g = lane >> 2;
    const int tig = lane & 3;
    const int rbase = w * 16;

    const int lrow = ((lane >> 3) & 1) * 8 + (lane & 7);
    const int lk8  = (lane >> 4) * 8;

    // ---- Q tile 64x64 halfs ----------------------------------------------------
#pragma unroll
    for (int it = 0; it < 4; it++) {
        int id = tid + it * 128;           // 0..511
        int r  = id >> 3;                  // 0..63
        int ch = id & 7;
        int n  = n0 + r;
        unsigned ok = (n < Nn) ? 16u : 0u;
        const __half* src = g_q + ((size_t)b * Nn + (n < Nn ? n : 0)) * Dd + h * dh + ch * 8;
        cp16(Qs + r * 36 + ch * 4, src, ok);
    }
    // ---- K and V tiles 144x64 halfs (rows >= CTX zero-filled) -------------------
#pragma unroll
    for (int it = 0; it < 18; it++) {
        int id = tid + it * 128;           // 0..2303
        int half = id & 1;                 // 0 = K, 1 = V
        int key  = (id >> 1) >> 3;         // 0..143
        int ch   = (id >> 1) & 7;
        unsigned ok = (key < CTX) ? 16u : 0u;
        const __half* src = g_kv + ((size_t)b * CTX + (key < CTX ? key : 0)) * (2 * Dd)
                          + half * Dd + h * dh + ch * 8;
        uint32_t* dst = (half ? Vs : Ks) + key * 36 + ch * 4;
        cp16(dst, src, ok);
    }
    cp_commit();
    cp_wait<0>();
    __syncthreads();

    // ---- phase 1: S = Q K^T -----------------------------------------------------
    uint32_t afr[4][4];
#pragma unroll
    for (int ks = 0; ks < 4; ks++)
        ldsm4(afr[ks][0], afr[ks][1], afr[ks][2], afr[ks][3],
              sQ + (uint32_t)((((rbase + lrow) * 72 + lk8) * 2) + ks * 32));

    float sacc[18][4];
#pragma unroll
    for (int nt = 0; nt < 18; nt++)
#pragma unroll
        for (int j = 0; j < 4; j++) sacc[nt][j] = 0.f;

    const uint32_t koff = sK + (uint32_t)((lrow * 72 + lk8) * 2);
#pragma unroll
    for (int ntp = 0; ntp < 9; ntp++) {
#pragma unroll
        for (int ks = 0; ks < 4; ks++) {
            uint32_t bfr[2][2];
            ldsm4(bfr[0][0], bfr[1][0], bfr[0][1], bfr[1][1],
                  koff + (uint32_t)(ntp * 2304 + ks * 32));
            mma_f16(sacc[2 * ntp],     afr[ks], bfr[0]);
            mma_f16(sacc[2 * ntp + 1], afr[ks], bfr[1]);
        }
    }

    // ---- exact softmax over 133 keys --------------------------------------------
    const float scale = 0.125f;
    float mlo = -1e30f, mhi = -1e30f;
#pragma unroll
    for (int nt = 0; nt < 18; nt++) {
        int c0 = nt * 8 + 2 * tig;
        float s0 = (c0     < CTX) ? sacc[nt][0] * scale : -1e30f;
        float s1 = (c0 + 1 < CTX) ? sacc[nt][1] * scale : -1e30f;
        float s2 = (c0     < CTX) ? sacc[nt][2] * scale : -1e30f;
        float s3 = (c0 + 1 < CTX) ? sacc[nt][3] * scale : -1e30f;
        sacc[nt][0] = s0; sacc[nt][1] = s1; sacc[nt][2] = s2; sacc[nt][3] = s3;
        mlo = fmaxf(mlo, fmaxf(s0, s1));
        mhi = fmaxf(mhi, fmaxf(s2, s3));
    }
    mlo = fmaxf(mlo, __shfl_xor_sync(0xffffffffu, mlo, 1));
    mlo = fmaxf(mlo, __shfl_xor_sync(0xffffffffu, mlo, 2));
    mhi = fmaxf(mhi, __shfl_xor_sync(0xffffffffu, mhi, 1));
    mhi = fmaxf(mhi, __shfl_xor_sync(0xffffffffu, mhi, 2));

    float llo = 0.f, lhi = 0.f;
#pragma unroll
    for (int nt = 0; nt < 18; nt++) {
        float p0 = __expf(sacc[nt][0] - mlo);
        float p1 = __expf(sacc[nt][1] - mlo);
        float p2 = __expf(sacc[nt][2] - mhi);
        float p3 = __expf(sacc[nt][3] - mhi);
        llo += p0 + p1; lhi += p2 + p3;
        sacc[nt][0] = p0; sacc[nt][1] = p1; sacc[nt][2] = p2; sacc[nt][3] = p3;
    }
    llo += __shfl_xor_sync(0xffffffffu, llo, 1);
    llo += __shfl_xor_sync(0xffffffffu, llo, 2);
    lhi += __shfl_xor_sync(0xffffffffu, lhi, 1);
    lhi += __shfl_xor_sync(0xffffffffu, lhi, 2);

    // ---- P -> smem (half pairs, 144 cols; pads are exp(-inf)=0) ------------------
#pragma unroll
    for (int nt = 0; nt < 18; nt++) {
        Ps[(rbase + g) * 76 + nt * 4 + tig]     = pk2(sacc[nt][0], sacc[nt][1]);
        Ps[(rbase + g + 8) * 76 + nt * 4 + tig] = pk2(sacc[nt][2], sacc[nt][3]);
    }
    __syncwarp();

    // ---- phase 2: O = P V (V via ldsm.trans) ------------------------------------
    float oacc[8][4];
#pragma unroll
    for (int nt = 0; nt < 8; nt++)
#pragma unroll
        for (int j = 0; j < 4; j++) oacc[nt][j] = 0.f;

    const uint32_t poff = sP + (uint32_t)(((rbase + lrow) * 152 + lk8) * 2);
    const uint32_t voff = sV + (uint32_t)(((((lane >> 4) & 1) * 8 + (lane & 7)) * 72
                                           + ((lane >> 3) & 1) * 8) * 2);
#pragma unroll
    for (int ks = 0; ks < 9; ks++) {
        uint32_t a2[4];
        ldsm4(a2[0], a2[1], a2[2], a2[3], poff + (uint32_t)(ks * 32));
#pragma unroll
        for (int ntp = 0; ntp < 4; ntp++) {
            uint32_t bfr[2][2];
            ldsm4t(bfr[0][0], bfr[1][0], bfr[0][1], bfr[1][1],
                   voff + (uint32_t)(ks * 2304 + ntp * 32));
            mma_f16(oacc[2 * ntp],     a2, bfr[0]);
            mma_f16(oacc[2 * ntp + 1], a2, bfr[1]);
        }
    }

    // ---- output y (half) ---------------------------------------------------------
    float invlo = 1.f / llo, invhi = 1.f / lhi;
    int row_lo = n0 + rbase + g;
    int row_hi = row_lo + 8;
#pragma unroll
    for (int nt = 0; nt < 8; nt++) {
        int col = h * dh + nt * 8 + 2 * tig;
        if (row_lo < Nn)
            *reinterpret_cast<uint32_t*>(&y[((size_t)b * Nn + row_lo) * Dd + col]) =
                pk2(oacc[nt][0] * invlo, oacc[nt][1] * invlo);
        if (row_hi < Nn)
            *reinterpret_cast<uint32_t*>(&y[((size_t)b * Nn + row_hi) * Dd + col]) =
                pk2(oacc[nt][2] * invhi, oacc[nt][3] * invhi);
    }
}

// ---------------- launch -----------------------------------------------------
extern "C" void kernel_launch(void* const* d_in, const int* in_sizes, int n_in,
                              void* d_out, int out_size)
{
    const float* x    = (const float*)d_in[0];
    const float* Qb   = (const float*)d_in[1];
    const float* Wq   = (const float*)d_in[2];
    const float* Wctx = (const float*)d_in[3];
    const float* bctx = (const float*)d_in[4];
    const float* Wout = (const float*)d_in[5];
    const float* bout = (const float*)d_in[6];
    const float* cent = (const float*)d_in[7];
    float* out = (float*)d_out;

    __half *p_xh, *p_wqT, *p_wctxT, *p_woutT, *p_qctx, *p_probs, *p_ctx, *p_kv, *p_q, *p_y;
    cudaGetSymbolAddress((void**)&p_xh,     g_xh);
    cudaGetSymbolAddress((void**)&p_wqT,    g_wqT);
    cudaGetSymbolAddress((void**)&p_wctxT,  g_wctxT);
    cudaGetSymbolAddress((void**)&p_woutT,  g_woutT);
    cudaGetSymbolAddress((void**)&p_qctx,   g_qctx);
    cudaGetSymbolAddress((void**)&p_probs,  g_probs);
    cudaGetSymbolAddress((void**)&p_ctx,    g_ctx);
    cudaGetSymbolAddress((void**)&p_kv,     g_kv);
    cudaGetSymbolAddress((void**)&p_q,      g_q);
    cudaGetSymbolAddress((void**)&p_y,      g_y);

    const int SMEM_NT  = (4 * 128 * 20 + 4 * 128 * 20) * 4;   // 81920
    const int SMEM_NN  = (4 * 128 * 20 + 4 * 32 * 68) * 4;    // 75776
    const int ATTN_SMEM = (64 * 36 + 144 * 36 + 144 * 36 + 64 * 76) * 4;  // 70144
    cudaFuncSetAttribute((const void*)hgemm<true,  false, true >, cudaFuncAttributeMaxDynamicSharedMemorySize, SMEM_NT);
    cudaFuncSetAttribute((const void*)hgemm<true,  true,  true >, cudaFuncAttributeMaxDynamicSharedMemorySize, SMEM_NT);
    cudaFuncSetAttribute((const void*)hgemm<true,  true,  false>, cudaFuncAttributeMaxDynamicSharedMemorySize, SMEM_NT);
    cudaFuncSetAttribute((const void*)hgemm<false, false, true >, cudaFuncAttributeMaxDynamicSharedMemorySize, SMEM_NN);
    cudaFuncSetAttribute((const void*)attn_mma, cudaFuncAttributeMaxDynamicSharedMemorySize, ATTN_SMEM);

    const size_t main_sz = (size_t)Bsz * Nn * Dd;
    float* cls_out = nullptr;
    float* idx_out = nullptr;
    if ((size_t)out_size >= main_sz + (size_t)Bsz * Dd + Bsz) {
        cls_out = out + main_sz;
        idx_out = out + main_sz + (size_t)Bsz * Dd;
    }

    cudaStream_t s2;
    cudaStreamCreateWithFlags(&s2, cudaStreamNonBlocking);
    cudaEvent_t e0, e1, e2, e3, e4;
    cudaEvent_t eA[NCH];
    cudaEventCreateWithFlags(&e0, cudaEventDisableTiming);
    cudaEventCreateWithFlags(&e1, cudaEventDisableTiming);
    cudaEventCreateWithFlags(&e2, cudaEventDisableTiming);
    cudaEventCreateWithFlags(&e3, cudaEventDisableTiming);
    cudaEventCreateWithFlags(&e4, cudaEventDisableTiming);
    for (int c = 0; c < NCH; c++)
        cudaEventCreateWithFlags(&eA[c], cudaEventDisableTiming);

    // ---- legal capture fork: record on capturing stream FIRST ----
    cudaEventRecord(e0, 0);
    cudaStreamWaitEvent(s2, e0, 0);

    // main: convert x -> half
    {
        int n4 = (int)(main_sz / 4);
        f2h_kernel<<<(n4 + 255) / 256, 256>>>((const float4*)x, (uint2*)p_xh, n4);
    }
    cudaEventRecord(e1, 0);

    // ---- side chain (s2): f2h-independent prologue, then q GEMM ----
    transpose_h<<<dim3(Dd / 32, Dd / 32), dim3(32, 8), 0, s2>>>(Wq, p_wqT, Dd, Dd);
    cls_kernel<<<Bsz, 256, 0, s2>>>(x, cent, cls_out, idx_out);
    gather_qctx_kernel<<<dim3(Kk * Dd / 4 / 256, Bsz), 256, 0, s2>>>(Qb);
    cudaEventRecord(e3, s2);                  // qctx ready
    cudaStreamWaitEvent(s2, e1, 0);           // need xh for q GEMM
    hgemm<true, false, true><<<dim3(Dd / 128, (Bsz * Nn + 127) / 128, 1), 256, SMEM_NT, s2>>>(
        p_xh, p_wqT, nullptr, p_q,
        Bsz * Nn, Dd, Dd, Dd, Dd, Dd, 0, 0, 0);
    cudaEventRecord(e2, s2);

    // ---- main chain: ctx pipeline ----
    transpose_h<<<dim3(2 * Dd / 32, Dd / 32), dim3(32, 8)>>>(Wctx, p_wctxT, Dd, 2 * Dd);
    transpose_h<<<dim3(Dd / 32, Dd / 32), dim3(32, 8)>>>(Wout, p_woutT, Dd, Dd);
    xreg_kernel<<<(Bsz * Rr * Dd / 2 + 255) / 256, 256>>>();

    cudaStreamWaitEvent(0, e3, 0);            // need qctx

    hgemm<true, false, true><<<dim3(Pp / 128, 1, Bsz), 256, SMEM_NT>>>(
        p_qctx, p_xh + (size_t)Rr * Dd, nullptr, p_probs,
        Kk, Pp, Dd, Dd, Dd, Pp,
        (long long)Kk * Dd, (long long)Nn * Dd, (long long)Kk * Pp);

    softmax_kernel<<<Bsz * Kk, 256>>>(p_probs);

    hgemm<false, false, true><<<dim3(Dd / 128, 1, Bsz), 256, SMEM_NN>>>(
        p_probs, p_xh + (size_t)Rr * Dd, nullptr, p_ctx + (size_t)Rr * Dd,
        Kk, Dd, Pp, Pp, Dd, Dd,
        (long long)Kk * Pp, (long long)Nn * Dd, (long long)CTX * Dd);

    hgemm<true, true, true><<<dim3((2 * Dd) / 128, (Bsz * CTX + 127) / 128, 1), 256, SMEM_NT>>>(
        p_ctx, p_wctxT, bctx, p_kv,
        Bsz * CTX, 2 * Dd, Dd, Dd, Dd, 2 * Dd, 0, 0, 0);

    // ---- join: attention needs q (s2) + kv (main) ----
    cudaStreamWaitEvent(0, e2, 0);

    // ---- chunked attention (main) -> out GEMM (s2) pipeline ----
    const int MCH = BCH * Nn;                 // 16464 rows per chunk
    for (int c = 0; c < NCH; c++) {
        attn_mma<<<dim3((Nn + 63) / 64, BCH * Hh), 128, ATTN_SMEM>>>(p_y, c * BCH);
        cudaEventRecord(eA[c], 0);
        cudaStreamWaitEvent(s2, eA[c], 0);
        hgemm<true, true, false><<<dim3(Dd / 128, (MCH + 127) / 128, 1), 256, SMEM_NT, s2>>>(
            p_y + (size_t)c * BCH * Nn * Dd, p_woutT, bout,
            out + (size_t)c * BCH * Nn * Dd,
            MCH, Dd, Dd, Dd, Dd, Dd, 0, 0, 0);
    }
    cudaEventRecord(e4, s2);
    cudaStreamWaitEvent(0, e4, 0);            // join before capture end

    cudaEventDestroy(e0);
    cudaEventDestroy(e1);
    cudaEventDestroy(e2);
    cudaEventDestroy(e3);
    cudaEventDestroy(e4);
    for (int c = 0; c < NCH; c++) cudaEventDestroy(eA[c]);
    cudaStreamDestroy(s2);
}

// round 12
// speedup vs baseline: 1.0252x; 1.0252x over previous
#include <cuda_runtime.h>
#include <cuda_fp16.h>
#include <math.h>
#include <stdint.h>

#define Bsz 64
#define Nn  1029
#define Dd  768
#define Hh  12
#define dh  64
#define Kk  128
#define Rr  5
#define Mm  4
#define Pp  1024          // N - R
#define CTX 133           // R + K
#define NT  17            // query tiles of 64 per (b,h)

// ---------------- scratch (static device globals: allocation-free) ----------
__device__ int    g_idx[Bsz];
__device__ __half g_xh[(size_t)Bsz * Nn * Dd];
__device__ __half g_wqT[Dd * Dd];
__device__ __half g_wctxT[2 * Dd * Dd];
__device__ __half g_woutT[Dd * Dd];
__device__ __half g_qctx[(size_t)Bsz * Kk * Dd];
__device__ __half g_probs[(size_t)Bsz * Kk * Pp];
__device__ __half g_ctx[(size_t)Bsz * CTX * Dd];
__device__ __half g_kv[(size_t)Bsz * CTX * 2 * Dd];
__device__ __half g_q[(size_t)Bsz * Nn * Dd];
__device__ __half g_y[(size_t)Bsz * Nn * Dd];

// ---------------- helpers ----------------------------------------------------
__device__ __forceinline__ uint32_t pk2(float a, float b) {
    __half2 h = __floats2half2_rn(a, b);
    return *reinterpret_cast<uint32_t*>(&h);
}

__device__ __forceinline__ void mma_f16(float* c, const uint32_t* a, const uint32_t* b) {
    asm volatile(
        "mma.sync.aligned.m16n8k16.row.col.f32.f16.f16.f32 "
        "{%0,%1,%2,%3}, {%4,%5,%6,%7}, {%8,%9}, {%0,%1,%2,%3};\n"
        : "+f"(c[0]), "+f"(c[1]), "+f"(c[2]), "+f"(c[3])
        : "r"(a[0]), "r"(a[1]), "r"(a[2]), "r"(a[3]), "r"(b[0]), "r"(b[1]));
}

__device__ __forceinline__ void ldsm4(uint32_t& r0, uint32_t& r1, uint32_t& r2,
                                      uint32_t& r3, uint32_t a) {
    asm volatile("ldmatrix.sync.aligned.m8n8.x4.shared.b16 {%0,%1,%2,%3}, [%4];"
                 : "=r"(r0), "=r"(r1), "=r"(r2), "=r"(r3) : "r"(a));
}
__device__ __forceinline__ void ldsm4t(uint32_t& r0, uint32_t& r1, uint32_t& r2,
                                       uint32_t& r3, uint32_t a) {
    asm volatile("ldmatrix.sync.aligned.m8n8.x4.trans.shared.b16 {%0,%1,%2,%3}, [%4];"
                 : "=r"(r0), "=r"(r1), "=r"(r2), "=r"(r3) : "r"(a));
}

__device__ __forceinline__ void cp16(void* smem_dst, const void* gsrc, unsigned bytes) {
    unsigned saddr = (unsigned)__cvta_generic_to_shared(smem_dst);
    asm volatile("cp.async.cg.shared.global [%0], [%1], 16, %2;\n"
                 :: "r"(saddr), "l"(gsrc), "r"(bytes));
}
__device__ __forceinline__ void cp_commit() { asm volatile("cp.async.commit_group;\n"); }
template<int N> __device__ __forceinline__ void cp_wait() {
    asm volatile("cp.async.wait_group %0;\n" :: "n"(N));
}

// ---------------- conversion kernels ------------------------------------------
__global__ void f2h_kernel(const float4* __restrict__ src, uint2* __restrict__ dst, int n4)
{
    int i = blockIdx.x * blockDim.x + threadIdx.x;
    if (i < n4) {
        float4 v = src[i];
        uint2 o;
        o.x = pk2(v.x, v.y);
        o.y = pk2(v.z, v.w);
        dst[i] = o;
    }
}

__global__ void transpose_h(const float* __restrict__ src, __half* __restrict__ dst,
                            int K, int N)
{
    __shared__ float t[32][33];
    int k0 = blockIdx.y * 32, n0 = blockIdx.x * 32;
    int tx = threadIdx.x, ty = threadIdx.y;   // 32 x 8
    for (int i = ty; i < 32; i += 8)
        t[i][tx] = src[(size_t)(k0 + i) * N + n0 + tx];
    __syncthreads();
    for (int i = ty; i < 32; i += 8)
        dst[(size_t)(n0 + i) * K + k0 + tx] = __float2half_rn(t[tx][i]);
}

// ---------------- cls_n, sims, argmax (fp32 exact) ---------------------------
__global__ void cls_kernel(const float* __restrict__ x,
                           const float* __restrict__ cent,
                           float* __restrict__ cls_out,
                           float* __restrict__ idx_out)
{
    int b = blockIdx.x;
    int tid = threadIdx.x;
    __shared__ float xs[Dd];
    __shared__ float red[256];
    __shared__ float sims[Mm];
    __shared__ float inv_s;

    float ss = 0.f;
    for (int i = tid; i < Dd; i += 256) {
        float v = x[(size_t)b * Nn * Dd + i];
        xs[i] = v;
        ss += v * v;
    }
    red[tid] = ss; __syncthreads();
    for (int s = 128; s > 0; s >>= 1) { if (tid < s) red[tid] += red[tid + s]; __syncthreads(); }
    if (tid == 0) inv_s = 1.f / fmaxf(sqrtf(red[0]), 1e-12f);
    __syncthreads();
    float inv = inv_s;

    for (int m = 0; m < Mm; m++) {
        float p = 0.f;
        for (int i = tid; i < Dd; i += 256) p += xs[i] * cent[m * Dd + i];
        red[tid] = p; __syncthreads();
        for (int s = 128; s > 0; s >>= 1) { if (tid < s) red[tid] += red[tid + s]; __syncthreads(); }
        if (tid == 0) sims[m] = red[0] * inv;
        __syncthreads();
    }
    if (tid == 0) {
        int best = 0; float bv = sims[0];
        for (int m = 1; m < Mm; m++) if (sims[m] > bv) { bv = sims[m]; best = m; }
        g_idx[b] = best;
        if (idx_out) idx_out[b] = (float)best;
    }
    if (cls_out)
        for (int i = tid; i < Dd; i += 256)
            cls_out[(size_t)b * Dd + i] = xs[i] * inv;
}

// ---------------- gather Q_banks[idx] (half, 2-D grid, float4) ---------------
__global__ void gather_qctx_kernel(const float* __restrict__ Qb)
{
    int b = blockIdx.y;
    int i4 = blockIdx.x * blockDim.x + threadIdx.x;
    const int n4 = Kk * Dd / 4;
    if (i4 < n4) {
        const float4 v = reinterpret_cast<const float4*>(
            Qb + (size_t)g_idx[b] * Kk * Dd)[i4];
        uint2 o;
        o.x = pk2(v.x, v.y);
        o.y = pk2(v.z, v.w);
        reinterpret_cast<uint2*>(g_qctx + (size_t)b * Kk * Dd)[i4] = o;
    }
}

__global__ void xreg_kernel()
{
    int i = blockIdx.x * blockDim.x + threadIdx.x;       // u32 units
    const int total = Bsz * Rr * Dd / 2;
    if (i < total) {
        int b = i / (Rr * Dd / 2);
        int r = i - b * (Rr * Dd / 2);
        reinterpret_cast<uint32_t*>(g_ctx)[(size_t)b * CTX * Dd / 2 + r] =
            reinterpret_cast<const uint32_t*>(g_xh)[(size_t)b * Nn * Dd / 2 + r];
    }
}

// ---------------- fp16 tensor-core GEMM, 4-stage cp.async + ldmatrix --------
template<bool TRANSB, bool BIAS, bool OUTHALF>
__global__ __launch_bounds__(256, 2)
void hgemm(const __half* __restrict__ A, const __half* __restrict__ Bm,
           const float* __restrict__ bias, void* __restrict__ Cv,
           int M, int N, int Kd, int lda, int ldb, int ldc,
           long long sA, long long sB, long long sC)
{
    extern __shared__ uint32_t smu[];
    const int ASTG = 128 * 20;
    const int BSTG = TRANSB ? 128 * 20 : 32 * 68;
    uint32_t* smA = smu;
    uint32_t* smB = smu + 4 * ASTG;
    const uint32_t sbA = (uint32_t)__cvta_generic_to_shared(smA);
    const uint32_t sbB = (uint32_t)__cvta_generic_to_shared(smB);

    const __half* Ab = A  + (long long)blockIdx.z * sA;
    const __half* Bb = Bm + (long long)blockIdx.z * sB;

    const int row0 = blockIdx.y * 128;
    const int col0 = blockIdx.x * 128;
    const int tid  = threadIdx.x;
    const int lane = tid & 31;
    const int warp = tid >> 5;
    const int wm = warp >> 1;
    const int wn = warp & 1;
    const int g   = lane >> 2;
    const int tig = lane & 3;

    const int lrow = ((lane >> 3) & 1) * 8 + (lane & 7);
    const int lk8  = (lane >> 4) * 8;
    uint32_t aoff[2], boff[4];
#pragma unroll
    for (int im = 0; im < 2; im++)
        aoff[im] = (uint32_t)(((wm * 32 + im * 16 + lrow) * 40 + lk8) * 2);
#pragma unroll
    for (int p = 0; p < 4; p++) {
        if (TRANSB)
            boff[p] = (uint32_t)(((wn * 64 + p * 16 + lrow) * 40 + lk8) * 2);
        else
            boff[p] = (uint32_t)(((((lane >> 4) & 1) * 8 + (lane & 7)) * 136
                                  + wn * 64 + p * 16 + ((lane >> 3) & 1) * 8) * 2);
    }

    float acc[2][8][4];
#pragma unroll
    for (int im = 0; im < 2; im++)
#pragma unroll
        for (int in = 0; in < 8; in++)
#pragma unroll
            for (int j = 0; j < 4; j++) acc[im][in][j] = 0.f;

    auto loadA = [&](int stg, int k0) {
        uint32_t* dst = smA + stg * ASTG;
#pragma unroll
        for (int it = 0; it < 2; it++) {
            int id = tid + it * 256;
            int r  = id >> 2;
            int c  = (id & 3) * 4;
            int gr = row0 + r;
            unsigned ok = (gr < M) ? 16u : 0u;
            const __half* src = Ab + (size_t)(gr < M ? gr : 0) * lda + k0 + c * 2;
            cp16(dst + r * 20 + c, src, ok);
        }
    };
    auto loadB = [&](int stg, int k0) {
        uint32_t* dst = smB + stg * BSTG;
#pragma unroll
        for (int it = 0; it < 2; it++) {
            int id = tid + it * 256;
            if (TRANSB) {
                int n = id >> 2;
                int c = (id & 3) * 4;
                cp16(dst + n * 20 + c, Bb + (size_t)(col0 + n) * ldb + k0 + c * 2, 16u);
            } else {
                int kr = id >> 4;
                int ch = id & 15;
                cp16(dst + kr * 68 + ch * 4, Bb + (size_t)(k0 + kr) * ldb + col0 + ch * 8, 16u);
            }
        }
    };

    loadA(0, 0);  loadB(0, 0);  cp_commit();
    loadA(1, 32); loadB(1, 32); cp_commit();
    loadA(2, 64); loadB(2, 64); cp_commit();

    const int nk = Kd >> 5;
    for (int i = 0; i < nk; i++) {
        int rem = nk - 1 - i;
        if (rem >= 2)      cp_wait<2>();
        else if (rem == 1) cp_wait<1>();
        else               cp_wait<0>();
        __syncthreads();
        if (i + 3 < nk) {
            int s4 = (i + 3) & 3;
            loadA(s4, (i + 3) * 32);
            loadB(s4, (i + 3) * 32);
            cp_commit();
        }

        const uint32_t baA = sbA + (uint32_t)((i & 3) * ASTG * 4);
        const uint32_t baB = sbB + (uint32_t)((i & 3) * BSTG * 4);

#pragma unroll
        for (int s = 0; s < 2; s++) {
            uint32_t afr[2][4], bfr[8][2];
#pragma unroll
            for (int im = 0; im < 2; im++)
                ldsm4(afr[im][0], afr[im][1], afr[im][2], afr[im][3],
                      baA + aoff[im] + s * 32);
#pragma unroll
            for (int p = 0; p < 4; p++) {
                if (TRANSB)
                    ldsm4(bfr[2 * p][0], bfr[2 * p + 1][0], bfr[2 * p][1], bfr[2 * p + 1][1],
                          baB + boff[p] + s * 32);
                else
                    ldsm4t(bfr[2 * p][0], bfr[2 * p + 1][0], bfr[2 * p][1], bfr[2 * p + 1][1],
                           baB + boff[p] + s * 4352);
            }
#pragma unroll
            for (int im = 0; im < 2; im++)
#pragma unroll
                for (int in = 0; in < 8; in++)
                    mma_f16(acc[im][in], afr[im], bfr[in]);
        }
        // trailing barrier elided: next iteration's leading barrier protects the ring
    }

#pragma unroll
    for (int im = 0; im < 2; im++) {
        int rb = row0 + wm * 32 + im * 16 + g;
#pragma unroll
        for (int in = 0; in < 8; in++) {
            int cb = col0 + wn * 64 + in * 8 + 2 * tig;
            float b0 = BIAS ? bias[cb] : 0.f;
            float b1 = BIAS ? bias[cb + 1] : 0.f;
            float v0 = acc[im][in][0] + b0, v1 = acc[im][in][1] + b1;
            float v2 = acc[im][in][2] + b0, v3 = acc[im][in][3] + b1;
            if (OUTHALF) {
                __half* C = (__half*)Cv + (long long)blockIdx.z * sC;
                if (rb < M)
                    *reinterpret_cast<uint32_t*>(&C[(size_t)rb * ldc + cb]) = pk2(v0, v1);
                if (rb + 8 < M)
                    *reinterpret_cast<uint32_t*>(&C[(size_t)(rb + 8) * ldc + cb]) = pk2(v2, v3);
            } else {
                float* C = (float*)Cv + (long long)blockIdx.z * sC;
                if (rb < M)
                    *reinterpret_cast<float2*>(&C[(size_t)rb * ldc + cb]) = make_float2(v0, v1);
                if (rb + 8 < M)
                    *reinterpret_cast<float2*>(&C[(size_t)(rb + 8) * ldc + cb]) = make_float2(v2, v3);
            }
        }
    }
}

// ---------------- row softmax over P=1024: half in-place ----------------------
__global__ void softmax_kernel(__half* __restrict__ pr)
{
    int row = blockIdx.x;
    uint2* p2 = reinterpret_cast<uint2*>(pr + (size_t)row * Pp);
    int tid = threadIdx.x;
    __shared__ float red[256];

    uint2 u = p2[tid];
    __half2 h0 = *reinterpret_cast<__half2*>(&u.x);
    __half2 h1 = *reinterpret_cast<__half2*>(&u.y);
    float vx = __low2float(h0), vy = __high2float(h0);
    float vz = __low2float(h1), vw = __high2float(h1);

    float mx = fmaxf(fmaxf(vx, vy), fmaxf(vz, vw));
    red[tid] = mx; __syncthreads();
    for (int st = 128; st > 0; st >>= 1) { if (tid < st) red[tid] = fmaxf(red[tid], red[tid + st]); __syncthreads(); }
    mx = red[0]; __syncthreads();

    vx = __expf(vx - mx); vy = __expf(vy - mx);
    vz = __expf(vz - mx); vw = __expf(vw - mx);
    float sm = vx + vy + vz + vw;
    red[tid] = sm; __syncthreads();
    for (int st = 128; st > 0; st >>= 1) { if (tid < st) red[tid] += red[tid + st]; __syncthreads(); }
    float inv = 1.f / red[0];
    uint2 o;
    o.x = pk2(vx * inv, vy * inv);
    o.y = pk2(vz * inv, vw * inv);
    p2[tid] = o;
}

// ---------------- fp16 fused attention: persistent per (b,h) ------------------
// grid (B*H), 128 threads (4 warps x 16 query rows = 64 queries per tile).
// K/V loaded ONCE into smem; loop over 17 query tiles with Q prefetch.
__global__ __launch_bounds__(128, 3)
void attn_mma(__half* __restrict__ y)
{
    extern __shared__ uint32_t smu[];
    uint32_t* Qs = smu;                    // [64][36] u32  (72-half pitch)
    uint32_t* Ks = smu + 64 * 36;          // [144][36]
    uint32_t* Vs = Ks + 144 * 36;          // [144][36]
    uint32_t* Ps = Vs + 144 * 36;          // [64][76] u32  (152-half pitch)
    const uint32_t sQ = (uint32_t)__cvta_generic_to_shared(Qs);
    const uint32_t sK = (uint32_t)__cvta_generic_to_shared(Ks);
    const uint32_t sV = (uint32_t)__cvta_generic_to_shared(Vs);
    const uint32_t sP = (uint32_t)__cvta_generic_to_shared(Ps);

    const int bh = blockIdx.x;
    const int b = bh / Hh, h = bh % Hh;
    const int tid = threadIdx.x;
    const int lane = tid & 31;
    const int w = tid >> 5;                // 0..3
    const int g = lane >> 2;
    const int tig = lane & 3;
    const int rbase = w * 16;

    const int lrow = ((lane >> 3) & 1) * 8 + (lane & 7);
    const int lk8  = (lane >> 4) * 8;

    const __half* qbase = g_q + (size_t)b * Nn * Dd + h * dh;

    auto loadQ = [&](int n0) {
#pragma unroll
        for (int it = 0; it < 4; it++) {
            int id = tid + it * 128;       // 0..511
            int r  = id >> 3;              // 0..63
            int ch = id & 7;
            int n  = n0 + r;
            unsigned ok = (n < Nn) ? 16u : 0u;
            cp16(Qs + r * 36 + ch * 4, qbase + (size_t)(n < Nn ? n : 0) * Dd + ch * 8, ok);
        }
    };

    // ---- K and V tiles 144x64 halfs, loaded once -------------------------------
#pragma unroll
    for (int it = 0; it < 18; it++) {
        int id = tid + it * 128;           // 0..2303
        int half = id & 1;                 // 0 = K, 1 = V
        int key  = (id >> 1) >> 3;         // 0..143
        int ch   = (id >> 1) & 7;
        unsigned ok = (key < CTX) ? 16u : 0u;
        const __half* src = g_kv + ((size_t)b * CTX + (key < CTX ? key : 0)) * (2 * Dd)
                          + half * Dd + h * dh + ch * 8;
        uint32_t* dst = (half ? Vs : Ks) + key * 36 + ch * 4;
        cp16(dst, src, ok);
    }
    loadQ(0);
    cp_commit();

    const uint32_t koff  = sK + (uint32_t)((lrow * 72 + lk8) * 2);
    const uint32_t qoff  = sQ + (uint32_t)(((rbase + lrow) * 72 + lk8) * 2);
    const uint32_t poff  = sP + (uint32_t)(((rbase + lrow) * 152 + lk8) * 2);
    const uint32_t voff  = sV + (uint32_t)(((((lane >> 4) & 1) * 8 + (lane & 7)) * 72
                                            + ((lane >> 3) & 1) * 8) * 2);
    const float scale = 0.125f;

    for (int t = 0; t < NT; t++) {
        const int n0 = t * 64;
        cp_wait<0>();
        __syncthreads();                   // Q tile t visible to all

        // Q fragments -> regs; then barrier so tile t+1 may overwrite Qs
        uint32_t afr[4][4];
#pragma unroll
        for (int ks = 0; ks < 4; ks++)
            ldsm4(afr[ks][0], afr[ks][1], afr[ks][2], afr[ks][3],
                  qoff + (uint32_t)(ks * 32));
        __syncthreads();
        if (t + 1 < NT) { loadQ(n0 + 64); cp_commit(); }

        // ---- phase 1: S = Q K^T -------------------------------------------------
        float sacc[18][4];
#pragma unroll
        for (int nt = 0; nt < 18; nt++)
#pragma unroll
            for (int j = 0; j < 4; j++) sacc[nt][j] = 0.f;

#pragma unroll
        for (int ntp = 0; ntp < 9; ntp++) {
#pragma unroll
            for (int ks = 0; ks < 4; ks++) {
                uint32_t bfr[2][2];
                ldsm4(bfr[0][0], bfr[1][0], bfr[0][1], bfr[1][1],
                      koff + (uint32_t)(ntp * 2304 + ks * 32));
                mma_f16(sacc[2 * ntp],     afr[ks], bfr[0]);
                mma_f16(sacc[2 * ntp + 1], afr[ks], bfr[1]);
            }
        }

        // ---- exact softmax over 133 keys ---------------------------------------
        float mlo = -1e30f, mhi = -1e30f;
#pragma unroll
        for (int nt = 0; nt < 18; nt++) {
            int c0 = nt * 8 + 2 * tig;
            float s0 = (c0     < CTX) ? sacc[nt][0] * scale : -1e30f;
            float s1 = (c0 + 1 < CTX) ? sacc[nt][1] * scale : -1e30f;
            float s2 = (c0     < CTX) ? sacc[nt][2] * scale : -1e30f;
            float s3 = (c0 + 1 < CTX) ? sacc[nt][3] * scale : -1e30f;
            sacc[nt][0] = s0; sacc[nt][1] = s1; sacc[nt][2] = s2; sacc[nt][3] = s3;
            mlo = fmaxf(mlo, fmaxf(s0, s1));
            mhi = fmaxf(mhi, fmaxf(s2, s3));
        }
        mlo = fmaxf(mlo, __shfl_xor_sync(0xffffffffu, mlo, 1));
        mlo = fmaxf(mlo, __shfl_xor_sync(0xffffffffu, mlo, 2));
        mhi = fmaxf(mhi, __shfl_xor_sync(0xffffffffu, mhi, 1));
        mhi = fmaxf(mhi, __shfl_xor_sync(0xffffffffu, mhi, 2));

        float llo = 0.f, lhi = 0.f;
#pragma unroll
        for (int nt = 0; nt < 18; nt++) {
            float p0 = __expf(sacc[nt][0] - mlo);
            float p1 = __expf(sacc[nt][1] - mlo);
            float p2 = __expf(sacc[nt][2] - mhi);
            float p3 = __expf(sacc[nt][3] - mhi);
            llo += p0 + p1; lhi += p2 + p3;
            sacc[nt][0] = p0; sacc[nt][1] = p1; sacc[nt][2] = p2; sacc[nt][3] = p3;
        }
        llo += __shfl_xor_sync(0xffffffffu, llo, 1);
        llo += __shfl_xor_sync(0xffffffffu, llo, 2);
        lhi += __shfl_xor_sync(0xffffffffu, lhi, 1);
        lhi += __shfl_xor_sync(0xffffffffu, lhi, 2);

        // ---- P -> smem (per-warp rows only) ------------------------------------
#pragma unroll
        for (int nt = 0; nt < 18; nt++) {
            Ps[(rbase + g) * 76 + nt * 4 + tig]     = pk2(sacc[nt][0], sacc[nt][1]);
            Ps[(rbase + g + 8) * 76 + nt * 4 + tig] = pk2(sacc[nt][2], sacc[nt][3]);
        }
        __syncwarp();

        // ---- phase 2: O = P V ---------------------------------------------------
        float oacc[8][4];
#pragma unroll
        for (int nt = 0; nt < 8; nt++)
#pragma unroll
            for (int j = 0; j < 4; j++) oacc[nt][j] = 0.f;

#pragma unroll
        for (int ks = 0; ks < 9; ks++) {
            uint32_t a2[4];
            ldsm4(a2[0], a2[1], a2[2], a2[3], poff + (uint32_t)(ks * 32));
#pragma unroll
            for (int ntp = 0; ntp < 4; ntp++) {
                uint32_t bfr[2][2];
                ldsm4t(bfr[0][0], bfr[1][0], bfr[0][1], bfr[1][1],
                       voff + (uint32_t)(ks * 2304 + ntp * 32));
                mma_f16(oacc[2 * ntp],     a2, bfr[0]);
                mma_f16(oacc[2 * ntp + 1], a2, bfr[1]);
            }
        }

        // ---- output y (half) ----------------------------------------------------
        float invlo = 1.f / llo, invhi = 1.f / lhi;
        int row_lo = n0 + rbase + g;
        int row_hi = row_lo + 8;
#pragma unroll
        for (int nt = 0; nt < 8; nt++) {
            int col = h * dh + nt * 8 + 2 * tig;
            if (row_lo < Nn)
                *reinterpret_cast<uint32_t*>(&y[((size_t)b * Nn + row_lo) * Dd + col]) =
                    pk2(oacc[nt][0] * invlo, oacc[nt][1] * invlo);
            if (row_hi < Nn)
                *reinterpret_cast<uint32_t*>(&y[((size_t)b * Nn + row_hi) * Dd + col]) =
                    pk2(oacc[nt][2] * invhi, oacc[nt][3] * invhi);
        }
    }
}

// ---------------- launch -----------------------------------------------------
extern "C" void kernel_launch(void* const* d_in, const int* in_sizes, int n_in,
                              void* d_out, int out_size)
{
    const float* x    = (const float*)d_in[0];
    const float* Qb   = (const float*)d_in[1];
    const float* Wq   = (const float*)d_in[2];
    const float* Wctx = (const float*)d_in[3];
    const float* bctx = (const float*)d_in[4];
    const float* Wout = (const float*)d_in[5];
    const float* bout = (const float*)d_in[6];
    const float* cent = (const float*)d_in[7];
    float* out = (float*)d_out;

    __half *p_xh, *p_wqT, *p_wctxT, *p_woutT, *p_qctx, *p_probs, *p_ctx, *p_kv, *p_q, *p_y;
    cudaGetSymbolAddress((void**)&p_xh,     g_xh);
    cudaGetSymbolAddress((void**)&p_wqT,    g_wqT);
    cudaGetSymbolAddress((void**)&p_wctxT,  g_wctxT);
    cudaGetSymbolAddress((void**)&p_woutT,  g_woutT);
    cudaGetSymbolAddress((void**)&p_qctx,   g_qctx);
    cudaGetSymbolAddress((void**)&p_probs,  g_probs);
    cudaGetSymbolAddress((void**)&p_ctx,    g_ctx);
    cudaGetSymbolAddress((void**)&p_kv,     g_kv);
    cudaGetSymbolAddress((void**)&p_q,      g_q);
    cudaGetSymbolAddress((void**)&p_y,      g_y);

    const int SMEM_NT  = (4 * 128 * 20 + 4 * 128 * 20) * 4;   // 81920
    const int SMEM_NN  = (4 * 128 * 20 + 4 * 32 * 68) * 4;    // 75776
    const int ATTN_SMEM = (64 * 36 + 144 * 36 + 144 * 36 + 64 * 76) * 4;  // 70144
    cudaFuncSetAttribute((const void*)hgemm<true,  false, true >, cudaFuncAttributeMaxDynamicSharedMemorySize, SMEM_NT);
    cudaFuncSetAttribute((const void*)hgemm<true,  true,  true >, cudaFuncAttributeMaxDynamicSharedMemorySize, SMEM_NT);
    cudaFuncSetAttribute((const void*)hgemm<true,  true,  false>, cudaFuncAttributeMaxDynamicSharedMemorySize, SMEM_NT);
    cudaFuncSetAttribute((const void*)hgemm<false, false, true >, cudaFuncAttributeMaxDynamicSharedMemorySize, SMEM_NN);
    cudaFuncSetAttribute((const void*)attn_mma, cudaFuncAttributeMaxDynamicSharedMemorySize, ATTN_SMEM);

    const size_t main_sz = (size_t)Bsz * Nn * Dd;
    float* cls_out = nullptr;
    float* idx_out = nullptr;
    if ((size_t)out_size >= main_sz + (size_t)Bsz * Dd + Bsz) {
        cls_out = out + main_sz;
        idx_out = out + main_sz + (size_t)Bsz * Dd;
    }

    cudaStream_t s2;
    cudaStreamCreateWithFlags(&s2, cudaStreamNonBlocking);
    cudaEvent_t e0, e1, e2, e3;
    cudaEventCreateWithFlags(&e0, cudaEventDisableTiming);
    cudaEventCreateWithFlags(&e1, cudaEventDisableTiming);
    cudaEventCreateWithFlags(&e2, cudaEventDisableTiming);
    cudaEventCreateWithFlags(&e3, cudaEventDisableTiming);

    // ---- legal capture fork: record on capturing stream FIRST ----
    cudaEventRecord(e0, 0);
    cudaStreamWaitEvent(s2, e0, 0);

    // main: convert x -> half
    {
        int n4 = (int)(main_sz / 4);
        f2h_kernel<<<(n4 + 255) / 256, 256>>>((const float4*)x, (uint2*)p_xh, n4);
    }
    cudaEventRecord(e1, 0);

    // ---- side chain (s2): f2h-independent prologue, then q GEMM ----
    transpose_h<<<dim3(Dd / 32, Dd / 32), dim3(32, 8), 0, s2>>>(Wq, p_wqT, Dd, Dd);
    cls_kernel<<<Bsz, 256, 0, s2>>>(x, cent, cls_out, idx_out);
    gather_qctx_kernel<<<dim3(Kk * Dd / 4 / 256, Bsz), 256, 0, s2>>>(Qb);
    cudaEventRecord(e3, s2);                  // qctx ready
    cudaStreamWaitEvent(s2, e1, 0);           // need xh for q GEMM
    hgemm<true, false, true><<<dim3(Dd / 128, (Bsz * Nn + 127) / 128, 1), 256, SMEM_NT, s2>>>(
        p_xh, p_wqT, nullptr, p_q,
        Bsz * Nn, Dd, Dd, Dd, Dd, Dd, 0, 0, 0);
    cudaEventRecord(e2, s2);

    // ---- main chain: ctx pipeline ----
    transpose_h<<<dim3(2 * Dd / 32, Dd / 32), dim3(32, 8)>>>(Wctx, p_wctxT, Dd, 2 * Dd);
    transpose_h<<<dim3(Dd / 32, Dd / 32), dim3(32, 8)>>>(Wout, p_woutT, Dd, Dd);
    xreg_kernel<<<(Bsz * Rr * Dd / 2 + 255) / 256, 256>>>();

    cudaStreamWaitEvent(0, e3, 0);            // need qctx

    hgemm<true, false, true><<<dim3(Pp / 128, 1, Bsz), 256, SMEM_NT>>>(
        p_qctx, p_xh + (size_t)Rr * Dd, nullptr, p_probs,
        Kk, Pp, Dd, Dd, Dd, Pp,
        (long long)Kk * Dd, (long long)Nn * Dd, (long long)Kk * Pp);

    softmax_kernel<<<Bsz * Kk, 256>>>(p_probs);

    hgemm<false, false, true><<<dim3(Dd / 128, 1, Bsz), 256, SMEM_NN>>>(
        p_probs, p_xh + (size_t)Rr * Dd, nullptr, p_ctx + (size_t)Rr * Dd,
        Kk, Dd, Pp, Pp, Dd, Dd,
        (long long)Kk * Pp, (long long)Nn * Dd, (long long)CTX * Dd);

    hgemm<true, true, true><<<dim3((2 * Dd) / 128, (Bsz * CTX + 127) / 128, 1), 256, SMEM_NT>>>(
        p_ctx, p_wctxT, bctx, p_kv,
        Bsz * CTX, 2 * Dd, Dd, Dd, Dd, 2 * Dd, 0, 0, 0);

    // ---- join: attention needs q (s2) + kv (main) ----
    cudaStreamWaitEvent(0, e2, 0);

    attn_mma<<<dim3(Bsz * Hh), 128, ATTN_SMEM>>>(p_y);

    hgemm<true, true, false><<<dim3(Dd / 128, (Bsz * Nn + 127) / 128, 1), 256, SMEM_NT>>>(
        p_y, p_woutT, bout, out,
        Bsz * Nn, Dd, Dd, Dd, Dd, Dd, 0, 0, 0);

    cudaEventDestroy(e0);
    cudaEventDestroy(e1);
    cudaEventDestroy(e2);
    cudaEventDestroy(e3);
    cudaStreamDestroy(s2);
}

// round 13
// speedup vs baseline: 1.0358x; 1.0103x over previous
#include <cuda_runtime.h>
#include <cuda_fp16.h>
#include <math.h>
#include <stdint.h>

#define Bsz 64
#define Nn  1029
#define Dd  768
#define Hh  12
#define dh  64
#define Kk  128
#define Rr  5
#define Mm  4
#define Pp  1024          // N - R
#define CTX 133           // R + K
#define NT  17            // query tiles of 64 per (b,h)

// ---------------- scratch (static device globals: allocation-free) ----------
__device__ int    g_idx[Bsz];
__device__ __half g_xh[(size_t)Bsz * Nn * Dd];
__device__ __half g_wqT[Dd * Dd];
__device__ __half g_wctxT[2 * Dd * Dd];
__device__ __half g_woutT[Dd * Dd];
__device__ __half g_qctx[(size_t)Bsz * Kk * Dd];
__device__ __half g_probs[(size_t)Bsz * Kk * Pp];
__device__ __half g_ctx[(size_t)Bsz * CTX * Dd];
__device__ __half g_kv[(size_t)Bsz * CTX * 2 * Dd];
__device__ __half g_q[(size_t)Bsz * Nn * Dd];
__device__ __half g_y[(size_t)Bsz * Nn * Dd];

// ---------------- helpers ----------------------------------------------------
__device__ __forceinline__ uint32_t pk2(float a, float b) {
    __half2 h = __floats2half2_rn(a, b);
    return *reinterpret_cast<uint32_t*>(&h);
}

__device__ __forceinline__ void mma_f16(float* c, const uint32_t* a, const uint32_t* b) {
    asm volatile(
        "mma.sync.aligned.m16n8k16.row.col.f32.f16.f16.f32 "
        "{%0,%1,%2,%3}, {%4,%5,%6,%7}, {%8,%9}, {%0,%1,%2,%3};\n"
        : "+f"(c[0]), "+f"(c[1]), "+f"(c[2]), "+f"(c[3])
        : "r"(a[0]), "r"(a[1]), "r"(a[2]), "r"(a[3]), "r"(b[0]), "r"(b[1]));
}

__device__ __forceinline__ void ldsm4(uint32_t& r0, uint32_t& r1, uint32_t& r2,
                                      uint32_t& r3, uint32_t a) {
    asm volatile("ldmatrix.sync.aligned.m8n8.x4.shared.b16 {%0,%1,%2,%3}, [%4];"
                 : "=r"(r0), "=r"(r1), "=r"(r2), "=r"(r3) : "r"(a));
}
__device__ __forceinline__ void ldsm4t(uint32_t& r0, uint32_t& r1, uint32_t& r2,
                                       uint32_t& r3, uint32_t a) {
    asm volatile("ldmatrix.sync.aligned.m8n8.x4.trans.shared.b16 {%0,%1,%2,%3}, [%4];"
                 : "=r"(r0), "=r"(r1), "=r"(r2), "=r"(r3) : "r"(a));
}

__device__ __forceinline__ void cp16(void* smem_dst, const void* gsrc, unsigned bytes) {
    unsigned saddr = (unsigned)__cvta_generic_to_shared(smem_dst);
    asm volatile("cp.async.cg.shared.global [%0], [%1], 16, %2;\n"
                 :: "r"(saddr), "l"(gsrc), "r"(bytes));
}
__device__ __forceinline__ void cp_commit() { asm volatile("cp.async.commit_group;\n"); }
template<int N> __device__ __forceinline__ void cp_wait() {
    asm volatile("cp.async.wait_group %0;\n" :: "n"(N));
}

// ---------------- conversion kernels ------------------------------------------
__global__ void f2h_kernel(const float4* __restrict__ src, uint2* __restrict__ dst, int n4)
{
    int i = blockIdx.x * blockDim.x + threadIdx.x;
    if (i < n4) {
        float4 v = src[i];
        uint2 o;
        o.x = pk2(v.x, v.y);
        o.y = pk2(v.z, v.w);
        dst[i] = o;
    }
}

__global__ void transpose_h(const float* __restrict__ src, __half* __restrict__ dst,
                            int K, int N)
{
    __shared__ float t[32][33];
    int k0 = blockIdx.y * 32, n0 = blockIdx.x * 32;
    int tx = threadIdx.x, ty = threadIdx.y;   // 32 x 8
    for (int i = ty; i < 32; i += 8)
        t[i][tx] = src[(size_t)(k0 + i) * N + n0 + tx];
    __syncthreads();
    for (int i = ty; i < 32; i += 8)
        dst[(size_t)(n0 + i) * K + k0 + tx] = __float2half_rn(t[tx][i]);
}

// ---------------- cls_n, sims, argmax (fp32 exact) ---------------------------
__global__ void cls_kernel(const float* __restrict__ x,
                           const float* __restrict__ cent,
                           float* __restrict__ cls_out,
                           float* __restrict__ idx_out)
{
    int b = blockIdx.x;
    int tid = threadIdx.x;
    __shared__ float xs[Dd];
    __shared__ float red[256];
    __shared__ float sims[Mm];
    __shared__ float inv_s;

    float ss = 0.f;
    for (int i = tid; i < Dd; i += 256) {
        float v = x[(size_t)b * Nn * Dd + i];
        xs[i] = v;
        ss += v * v;
    }
    red[tid] = ss; __syncthreads();
    for (int s = 128; s > 0; s >>= 1) { if (tid < s) red[tid] += red[tid + s]; __syncthreads(); }
    if (tid == 0) inv_s = 1.f / fmaxf(sqrtf(red[0]), 1e-12f);
    __syncthreads();
    float inv = inv_s;

    for (int m = 0; m < Mm; m++) {
        float p = 0.f;
        for (int i = tid; i < Dd; i += 256) p += xs[i] * cent[m * Dd + i];
        red[tid] = p; __syncthreads();
        for (int s = 128; s > 0; s >>= 1) { if (tid < s) red[tid] += red[tid + s]; __syncthreads(); }
        if (tid == 0) sims[m] = red[0] * inv;
        __syncthreads();
    }
    if (tid == 0) {
        int best = 0; float bv = sims[0];
        for (int m = 1; m < Mm; m++) if (sims[m] > bv) { bv = sims[m]; best = m; }
        g_idx[b] = best;
        if (idx_out) idx_out[b] = (float)best;
    }
    if (cls_out)
        for (int i = tid; i < Dd; i += 256)
            cls_out[(size_t)b * Dd + i] = xs[i] * inv;
}

// ---------------- gather Q_banks[idx] (half, 2-D grid, float4) ---------------
__global__ void gather_qctx_kernel(const float* __restrict__ Qb)
{
    int b = blockIdx.y;
    int i4 = blockIdx.x * blockDim.x + threadIdx.x;
    const int n4 = Kk * Dd / 4;
    if (i4 < n4) {
        const float4 v = reinterpret_cast<const float4*>(
            Qb + (size_t)g_idx[b] * Kk * Dd)[i4];
        uint2 o;
        o.x = pk2(v.x, v.y);
        o.y = pk2(v.z, v.w);
        reinterpret_cast<uint2*>(g_qctx + (size_t)b * Kk * Dd)[i4] = o;
    }
}

__global__ void xreg_kernel()
{
    int i = blockIdx.x * blockDim.x + threadIdx.x;       // u32 units
    const int total = Bsz * Rr * Dd / 2;
    if (i < total) {
        int b = i / (Rr * Dd / 2);
        int r = i - b * (Rr * Dd / 2);
        reinterpret_cast<uint32_t*>(g_ctx)[(size_t)b * CTX * Dd / 2 + r] =
            reinterpret_cast<const uint32_t*>(g_xh)[(size_t)b * Nn * Dd / 2 + r];
    }
}

// ---------------- fp16 tensor-core GEMM, 5-stage cp.async + ldmatrix --------
template<bool TRANSB, bool BIAS, bool OUTHALF>
__global__ __launch_bounds__(256, 2)
void hgemm(const __half* __restrict__ A, const __half* __restrict__ Bm,
           const float* __restrict__ bias, void* __restrict__ Cv,
           int M, int N, int Kd, int lda, int ldb, int ldc,
           long long sA, long long sB, long long sC)
{
    extern __shared__ uint32_t smu[];
    const int ASTG = 128 * 20;
    const int BSTG = TRANSB ? 128 * 20 : 32 * 68;
    uint32_t* smA = smu;
    uint32_t* smB = smu + 5 * ASTG;
    const uint32_t sbA = (uint32_t)__cvta_generic_to_shared(smA);
    const uint32_t sbB = (uint32_t)__cvta_generic_to_shared(smB);

    const __half* Ab = A  + (long long)blockIdx.z * sA;
    const __half* Bb = Bm + (long long)blockIdx.z * sB;

    const int row0 = blockIdx.y * 128;
    const int col0 = blockIdx.x * 128;
    const int tid  = threadIdx.x;
    const int lane = tid & 31;
    const int warp = tid >> 5;
    const int wm = warp >> 1;
    const int wn = warp & 1;
    const int g   = lane >> 2;
    const int tig = lane & 3;

    const int lrow = ((lane >> 3) & 1) * 8 + (lane & 7);
    const int lk8  = (lane >> 4) * 8;
    uint32_t aoff[2], boff[4];
#pragma unroll
    for (int im = 0; im < 2; im++)
        aoff[im] = (uint32_t)(((wm * 32 + im * 16 + lrow) * 40 + lk8) * 2);
#pragma unroll
    for (int p = 0; p < 4; p++) {
        if (TRANSB)
            boff[p] = (uint32_t)(((wn * 64 + p * 16 + lrow) * 40 + lk8) * 2);
        else
            boff[p] = (uint32_t)(((((lane >> 4) & 1) * 8 + (lane & 7)) * 136
                                  + wn * 64 + p * 16 + ((lane >> 3) & 1) * 8) * 2);
    }

    float acc[2][8][4];
#pragma unroll
    for (int im = 0; im < 2; im++)
#pragma unroll
        for (int in = 0; in < 8; in++)
#pragma unroll
            for (int j = 0; j < 4; j++) acc[im][in][j] = 0.f;

    auto loadA = [&](int stg, int k0) {
        uint32_t* dst = smA + stg * ASTG;
#pragma unroll
        for (int it = 0; it < 2; it++) {
            int id = tid + it * 256;
            int r  = id >> 2;
            int c  = (id & 3) * 4;
            int gr = row0 + r;
            unsigned ok = (gr < M) ? 16u : 0u;
            const __half* src = Ab + (size_t)(gr < M ? gr : 0) * lda + k0 + c * 2;
            cp16(dst + r * 20 + c, src, ok);
        }
    };
    auto loadB = [&](int stg, int k0) {
        uint32_t* dst = smB + stg * BSTG;
#pragma unroll
        for (int it = 0; it < 2; it++) {
            int id = tid + it * 256;
            if (TRANSB) {
                int n = id >> 2;
                int c = (id & 3) * 4;
                cp16(dst + n * 20 + c, Bb + (size_t)(col0 + n) * ldb + k0 + c * 2, 16u);
            } else {
                int kr = id >> 4;
                int ch = id & 15;
                cp16(dst + kr * 68 + ch * 4, Bb + (size_t)(k0 + kr) * ldb + col0 + ch * 8, 16u);
            }
        }
    };

    const int nk = Kd >> 5;
    loadA(0, 0);  loadB(0, 0);  cp_commit();
    loadA(1, 32); loadB(1, 32); cp_commit();
    loadA(2, 64); loadB(2, 64); cp_commit();
    loadA(3, 96); loadB(3, 96); cp_commit();

    for (int i = 0; i < nk; i++) {
        int rem = nk - 1 - i;
        if (rem >= 3)      cp_wait<3>();
        else if (rem == 2) cp_wait<2>();
        else if (rem == 1) cp_wait<1>();
        else               cp_wait<0>();
        __syncthreads();
        if (i + 4 < nk) {
            int s5 = (i + 4) % 5;
            loadA(s5, (i + 4) * 32);
            loadB(s5, (i + 4) * 32);
            cp_commit();
        }

        const uint32_t baA = sbA + (uint32_t)((i % 5) * ASTG * 4);
        const uint32_t baB = sbB + (uint32_t)((i % 5) * BSTG * 4);

#pragma unroll
        for (int s = 0; s < 2; s++) {
            uint32_t afr[2][4], bfr[8][2];
#pragma unroll
            for (int im = 0; im < 2; im++)
                ldsm4(afr[im][0], afr[im][1], afr[im][2], afr[im][3],
                      baA + aoff[im] + s * 32);
#pragma unroll
            for (int p = 0; p < 4; p++) {
                if (TRANSB)
                    ldsm4(bfr[2 * p][0], bfr[2 * p + 1][0], bfr[2 * p][1], bfr[2 * p + 1][1],
                          baB + boff[p] + s * 32);
                else
                    ldsm4t(bfr[2 * p][0], bfr[2 * p + 1][0], bfr[2 * p][1], bfr[2 * p + 1][1],
                           baB + boff[p] + s * 4352);
            }
#pragma unroll
            for (int im = 0; im < 2; im++)
#pragma unroll
                for (int in = 0; in < 8; in++)
                    mma_f16(acc[im][in], afr[im], bfr[in]);
        }
        // trailing barrier elided: writes at iter i target stage (i+4)%5 whose
        // last readers (iter i-1) passed this iteration's leading barrier.
    }

#pragma unroll
    for (int im = 0; im < 2; im++) {
        int rb = row0 + wm * 32 + im * 16 + g;
#pragma unroll
        for (int in = 0; in < 8; in++) {
            int cb = col0 + wn * 64 + in * 8 + 2 * tig;
            float b0 = BIAS ? bias[cb] : 0.f;
            float b1 = BIAS ? bias[cb + 1] : 0.f;
            float v0 = acc[im][in][0] + b0, v1 = acc[im][in][1] + b1;
            float v2 = acc[im][in][2] + b0, v3 = acc[im][in][3] + b1;
            if (OUTHALF) {
                __half* C = (__half*)Cv + (long long)blockIdx.z * sC;
                if (rb < M)
                    *reinterpret_cast<uint32_t*>(&C[(size_t)rb * ldc + cb]) = pk2(v0, v1);
                if (rb + 8 < M)
                    *reinterpret_cast<uint32_t*>(&C[(size_t)(rb + 8) * ldc + cb]) = pk2(v2, v3);
            } else {
                float* C = (float*)Cv + (long long)blockIdx.z * sC;
                if (rb < M)
                    *reinterpret_cast<float2*>(&C[(size_t)rb * ldc + cb]) = make_float2(v0, v1);
                if (rb + 8 < M)
                    *reinterpret_cast<float2*>(&C[(size_t)(rb + 8) * ldc + cb]) = make_float2(v2, v3);
            }
        }
    }
}

// ---------------- row softmax over P=1024: half in-place ----------------------
__global__ void softmax_kernel(__half* __restrict__ pr)
{
    int row = blockIdx.x;
    uint2* p2 = reinterpret_cast<uint2*>(pr + (size_t)row * Pp);
    int tid = threadIdx.x;
    __shared__ float red[256];

    uint2 u = p2[tid];
    __half2 h0 = *reinterpret_cast<__half2*>(&u.x);
    __half2 h1 = *reinterpret_cast<__half2*>(&u.y);
    float vx = __low2float(h0), vy = __high2float(h0);
    float vz = __low2float(h1), vw = __high2float(h1);

    float mx = fmaxf(fmaxf(vx, vy), fmaxf(vz, vw));
    red[tid] = mx; __syncthreads();
    for (int st = 128; st > 0; st >>= 1) { if (tid < st) red[tid] = fmaxf(red[tid], red[tid + st]); __syncthreads(); }
    mx = red[0]; __syncthreads();

    vx = __expf(vx - mx); vy = __expf(vy - mx);
    vz = __expf(vz - mx); vw = __expf(vw - mx);
    float sm = vx + vy + vz + vw;
    red[tid] = sm; __syncthreads();
    for (int st = 128; st > 0; st >>= 1) { if (tid < st) red[tid] += red[tid + st]; __syncthreads(); }
    float inv = 1.f / red[0];
    uint2 o;
    o.x = pk2(vx * inv, vy * inv);
    o.y = pk2(vz * inv, vw * inv);
    p2[tid] = o;
}

// ---------------- fp16 fused attention: persistent per (b,h) ------------------
// grid (B*H), 128 threads (4 warps x 16 query rows = 64 queries per tile).
// K/V loaded ONCE; loop over 17 query tiles with Q prefetch; y stored via
// smem staging for fully coalesced 16B row writes.
__global__ __launch_bounds__(128, 3)
void attn_mma(__half* __restrict__ y)
{
    extern __shared__ uint32_t smu[];
    uint32_t* Qs = smu;                    // [64][36] u32  (72-half pitch)
    uint32_t* Ks = smu + 64 * 36;          // [144][36]
    uint32_t* Vs = Ks + 144 * 36;          // [144][36]
    uint32_t* Ps = Vs + 144 * 36;          // [64][76] u32  (152-half pitch)
    const uint32_t sQ = (uint32_t)__cvta_generic_to_shared(Qs);
    const uint32_t sK = (uint32_t)__cvta_generic_to_shared(Ks);
    const uint32_t sV = (uint32_t)__cvta_generic_to_shared(Vs);
    const uint32_t sP = (uint32_t)__cvta_generic_to_shared(Ps);

    const int bh = blockIdx.x;
    const int b = bh / Hh, h = bh % Hh;
    const int tid = threadIdx.x;
    const int lane = tid & 31;
    const int w = tid >> 5;                // 0..3
    const int g = lane >> 2;
    const int tig = lane & 3;
    const int rbase = w * 16;

    const int lrow = ((lane >> 3) & 1) * 8 + (lane & 7);
    const int lk8  = (lane >> 4) * 8;

    const __half* qbase = g_q + (size_t)b * Nn * Dd + h * dh;

    auto loadQ = [&](int n0) {
#pragma unroll
        for (int it = 0; it < 4; it++) {
            int id = tid + it * 128;       // 0..511
            int r  = id >> 3;              // 0..63
            int ch = id & 7;
            int n  = n0 + r;
            unsigned ok = (n < Nn) ? 16u : 0u;
            cp16(Qs + r * 36 + ch * 4, qbase + (size_t)(n < Nn ? n : 0) * Dd + ch * 8, ok);
        }
    };

    // ---- K and V tiles 144x64 halfs, loaded once -------------------------------
#pragma unroll
    for (int it = 0; it < 18; it++) {
        int id = tid + it * 128;           // 0..2303
        int half = id & 1;                 // 0 = K, 1 = V
        int key  = (id >> 1) >> 3;         // 0..143
        int ch   = (id >> 1) & 7;
        unsigned ok = (key < CTX) ? 16u : 0u;
        const __half* src = g_kv + ((size_t)b * CTX + (key < CTX ? key : 0)) * (2 * Dd)
                          + half * Dd + h * dh + ch * 8;
        uint32_t* dst = (half ? Vs : Ks) + key * 36 + ch * 4;
        cp16(dst, src, ok);
    }
    loadQ(0);
    cp_commit();

    const uint32_t koff  = sK + (uint32_t)((lrow * 72 + lk8) * 2);
    const uint32_t qoff  = sQ + (uint32_t)(((rbase + lrow) * 72 + lk8) * 2);
    const uint32_t poff  = sP + (uint32_t)(((rbase + lrow) * 152 + lk8) * 2);
    const uint32_t voff  = sV + (uint32_t)(((((lane >> 4) & 1) * 8 + (lane & 7)) * 72
                                            + ((lane >> 3) & 1) * 8) * 2);
    const float scale = 0.125f;

    for (int t = 0; t < NT; t++) {
        const int n0 = t * 64;
        cp_wait<0>();
        __syncthreads();                   // Q tile t visible to all

        uint32_t afr[4][4];
#pragma unroll
        for (int ks = 0; ks < 4; ks++)
            ldsm4(afr[ks][0], afr[ks][1], afr[ks][2], afr[ks][3],
                  qoff + (uint32_t)(ks * 32));
        __syncthreads();
        if (t + 1 < NT) { loadQ(n0 + 64); cp_commit(); }

        // ---- phase 1: S = Q K^T -------------------------------------------------
        float sacc[18][4];
#pragma unroll
        for (int nt = 0; nt < 18; nt++)
#pragma unroll
            for (int j = 0; j < 4; j++) sacc[nt][j] = 0.f;

#pragma unroll
        for (int ntp = 0; ntp < 9; ntp++) {
#pragma unroll
            for (int ks = 0; ks < 4; ks++) {
                uint32_t bfr[2][2];
                ldsm4(bfr[0][0], bfr[1][0], bfr[0][1], bfr[1][1],
                      koff + (uint32_t)(ntp * 2304 + ks * 32));
                mma_f16(sacc[2 * ntp],     afr[ks], bfr[0]);
                mma_f16(sacc[2 * ntp + 1], afr[ks], bfr[1]);
            }
        }

        // ---- exact softmax over 133 keys ---------------------------------------
        float mlo = -1e30f, mhi = -1e30f;
#pragma unroll
        for (int nt = 0; nt < 18; nt++) {
            int c0 = nt * 8 + 2 * tig;
            float s0 = (c0     < CTX) ? sacc[nt][0] * scale : -1e30f;
            float s1 = (c0 + 1 < CTX) ? sacc[nt][1] * scale : -1e30f;
            float s2 = (c0     < CTX) ? sacc[nt][2] * scale : -1e30f;
            float s3 = (c0 + 1 < CTX) ? sacc[nt][3] * scale : -1e30f;
            sacc[nt][0] = s0; sacc[nt][1] = s1; sacc[nt][2] = s2; sacc[nt][3] = s3;
            mlo = fmaxf(mlo, fmaxf(s0, s1));
            mhi = fmaxf(mhi, fmaxf(s2, s3));
        }
        mlo = fmaxf(mlo, __shfl_xor_sync(0xffffffffu, mlo, 1));
        mlo = fmaxf(mlo, __shfl_xor_sync(0xffffffffu, mlo, 2));
        mhi = fmaxf(mhi, __shfl_xor_sync(0xffffffffu, mhi, 1));
        mhi = fmaxf(mhi, __shfl_xor_sync(0xffffffffu, mhi, 2));

        float llo = 0.f, lhi = 0.f;
#pragma unroll
        for (int nt = 0; nt < 18; nt++) {
            float p0 = __expf(sacc[nt][0] - mlo);
            float p1 = __expf(sacc[nt][1] - mlo);
            float p2 = __expf(sacc[nt][2] - mhi);
            float p3 = __expf(sacc[nt][3] - mhi);
            llo += p0 + p1; lhi += p2 + p3;
            sacc[nt][0] = p0; sacc[nt][1] = p1; sacc[nt][2] = p2; sacc[nt][3] = p3;
        }
        llo += __shfl_xor_sync(0xffffffffu, llo, 1);
        llo += __shfl_xor_sync(0xffffffffu, llo, 2);
        lhi += __shfl_xor_sync(0xffffffffu, lhi, 1);
        lhi += __shfl_xor_sync(0xffffffffu, lhi, 2);

        // ---- P -> smem (per-warp rows only) ------------------------------------
#pragma unroll
        for (int nt = 0; nt < 18; nt++) {
            Ps[(rbase + g) * 76 + nt * 4 + tig]     = pk2(sacc[nt][0], sacc[nt][1]);
            Ps[(rbase + g + 8) * 76 + nt * 4 + tig] = pk2(sacc[nt][2], sacc[nt][3]);
        }
        __syncwarp();

        // ---- phase 2: O = P V ---------------------------------------------------
        float oacc[8][4];
#pragma unroll
        for (int nt = 0; nt < 8; nt++)
#pragma unroll
            for (int j = 0; j < 4; j++) oacc[nt][j] = 0.f;

#pragma unroll
        for (int ks = 0; ks < 9; ks++) {
            uint32_t a2[4];
            ldsm4(a2[0], a2[1], a2[2], a2[3], poff + (uint32_t)(ks * 32));
#pragma unroll
            for (int ntp = 0; ntp < 4; ntp++) {
                uint32_t bfr[2][2];
                ldsm4t(bfr[0][0], bfr[1][0], bfr[0][1], bfr[1][1],
                       voff + (uint32_t)(ks * 2304 + ntp * 32));
                mma_f16(oacc[2 * ntp],     a2, bfr[0]);
                mma_f16(oacc[2 * ntp + 1], a2, bfr[1]);
            }
        }

        // ---- stage O into Ps (own rows) then coalesced 16B row stores -----------
        float invlo = 1.f / llo, invhi = 1.f / lhi;
        __syncwarp();                      // phase-2 reads of Ps rows done
#pragma unroll
        for (int nt = 0; nt < 8; nt++) {
            Ps[(rbase + g) * 76 + nt * 4 + tig]     = pk2(oacc[nt][0] * invlo, oacc[nt][1] * invlo);
            Ps[(rbase + g + 8) * 76 + nt * 4 + tig] = pk2(oacc[nt][2] * invhi, oacc[nt][3] * invhi);
        }
        __syncwarp();
#pragma unroll
        for (int it = 0; it < 4; it++) {
            int id = lane + it * 32;       // 0..127
            int r  = id >> 3;              // 0..15 (own warp's rows)
            int ch = id & 7;               // 16B chunk
            int n  = n0 + rbase + r;
            if (n < Nn) {
                uint4 v = *reinterpret_cast<const uint4*>(&Ps[(rbase + r) * 76 + ch * 4]);
                *reinterpret_cast<uint4*>(&y[((size_t)b * Nn + n) * Dd + h * dh + ch * 8]) = v;
            }
        }
    }
}

// ---------------- launch -----------------------------------------------------
extern "C" void kernel_launch(void* const* d_in, const int* in_sizes, int n_in,
                              void* d_out, int out_size)
{
    const float* x    = (const float*)d_in[0];
    const float* Qb   = (const float*)d_in[1];
    const float* Wq   = (const float*)d_in[2];
    const float* Wctx = (const float*)d_in[3];
    const float* bctx = (const float*)d_in[4];
    const float* Wout = (const float*)d_in[5];
    const float* bout = (const float*)d_in[6];
    const float* cent = (const float*)d_in[7];
    float* out = (float*)d_out;

    __half *p_xh, *p_wqT, *p_wctxT, *p_woutT, *p_qctx, *p_probs, *p_ctx, *p_kv, *p_q, *p_y;
    cudaGetSymbolAddress((void**)&p_xh,     g_xh);
    cudaGetSymbolAddress((void**)&p_wqT,    g_wqT);
    cudaGetSymbolAddress((void**)&p_wctxT,  g_wctxT);
    cudaGetSymbolAddress((void**)&p_woutT,  g_woutT);
    cudaGetSymbolAddress((void**)&p_qctx,   g_qctx);
    cudaGetSymbolAddress((void**)&p_probs,  g_probs);
    cudaGetSymbolAddress((void**)&p_ctx,    g_ctx);
    cudaGetSymbolAddress((void**)&p_kv,     g_kv);
    cudaGetSymbolAddress((void**)&p_q,      g_q);
    cudaGetSymbolAddress((void**)&p_y,      g_y);

    const int SMEM_NT  = (5 * 128 * 20 + 5 * 128 * 20) * 4;   // 102400
    const int SMEM_NN  = (5 * 128 * 20 + 5 * 32 * 68) * 4;    // 94720
    const int ATTN_SMEM = (64 * 36 + 144 * 36 + 144 * 36 + 64 * 76) * 4;  // 70144
    cudaFuncSetAttribute((const void*)hgemm<true,  false, true >, cudaFuncAttributeMaxDynamicSharedMemorySize, SMEM_NT);
    cudaFuncSetAttribute((const void*)hgemm<true,  true,  true >, cudaFuncAttributeMaxDynamicSharedMemorySize, SMEM_NT);
    cudaFuncSetAttribute((const void*)hgemm<true,  true,  false>, cudaFuncAttributeMaxDynamicSharedMemorySize, SMEM_NT);
    cudaFuncSetAttribute((const void*)hgemm<false, false, true >, cudaFuncAttributeMaxDynamicSharedMemorySize, SMEM_NN);
    cudaFuncSetAttribute((const void*)attn_mma, cudaFuncAttributeMaxDynamicSharedMemorySize, ATTN_SMEM);

    const size_t main_sz = (size_t)Bsz * Nn * Dd;
    float* cls_out = nullptr;
    float* idx_out = nullptr;
    if ((size_t)out_size >= main_sz + (size_t)Bsz * Dd + Bsz) {
        cls_out = out + main_sz;
        idx_out = out + main_sz + (size_t)Bsz * Dd;
    }

    cudaStream_t s2;
    cudaStreamCreateWithFlags(&s2, cudaStreamNonBlocking);
    cudaEvent_t e0, e1, e2, e3;
    cudaEventCreateWithFlags(&e0, cudaEventDisableTiming);
    cudaEventCreateWithFlags(&e1, cudaEventDisableTiming);
    cudaEventCreateWithFlags(&e2, cudaEventDisableTiming);
    cudaEventCreateWithFlags(&e3, cudaEventDisableTiming);

    // ---- legal capture fork: record on capturing stream FIRST ----
    cudaEventRecord(e0, 0);
    cudaStreamWaitEvent(s2, e0, 0);

    // main: convert x -> half
    {
        int n4 = (int)(main_sz / 4);
        f2h_kernel<<<(n4 + 255) / 256, 256>>>((const float4*)x, (uint2*)p_xh, n4);
    }
    cudaEventRecord(e1, 0);

    // ---- side chain (s2): f2h-independent prologue, then q GEMM ----
    transpose_h<<<dim3(Dd / 32, Dd / 32), dim3(32, 8), 0, s2>>>(Wq, p_wqT, Dd, Dd);
    cls_kernel<<<Bsz, 256, 0, s2>>>(x, cent, cls_out, idx_out);
    gather_qctx_kernel<<<dim3(Kk * Dd / 4 / 256, Bsz), 256, 0, s2>>>(Qb);
    cudaEventRecord(e3, s2);                  // qctx ready
    cudaStreamWaitEvent(s2, e1, 0);           // need xh for q GEMM
    hgemm<true, false, true><<<dim3(Dd / 128, (Bsz * Nn + 127) / 128, 1), 256, SMEM_NT, s2>>>(
        p_xh, p_wqT, nullptr, p_q,
        Bsz * Nn, Dd, Dd, Dd, Dd, Dd, 0, 0, 0);
    cudaEventRecord(e2, s2);

    // ---- main chain: ctx pipeline ----
    transpose_h<<<dim3(2 * Dd / 32, Dd / 32), dim3(32, 8)>>>(Wctx, p_wctxT, Dd, 2 * Dd);
    transpose_h<<<dim3(Dd / 32, Dd / 32), dim3(32, 8)>>>(Wout, p_woutT, Dd, Dd);
    xreg_kernel<<<(Bsz * Rr * Dd / 2 + 255) / 256, 256>>>();

    cudaStreamWaitEvent(0, e3, 0);            // need qctx

    hgemm<true, false, true><<<dim3(Pp / 128, 1, Bsz), 256, SMEM_NT>>>(
        p_qctx, p_xh + (size_t)Rr * Dd, nullptr, p_probs,
        Kk, Pp, Dd, Dd, Dd, Pp,
        (long long)Kk * Dd, (long long)Nn * Dd, (long long)Kk * Pp);

    softmax_kernel<<<Bsz * Kk, 256>>>(p_probs);

    hgemm<false, false, true><<<dim3(Dd / 128, 1, Bsz), 256, SMEM_NN>>>(
        p_probs, p_xh + (size_t)Rr * Dd, nullptr, p_ctx + (size_t)Rr * Dd,
        Kk, Dd, Pp, Pp, Dd, Dd,
        (long long)Kk * Pp, (long long)Nn * Dd, (long long)CTX * Dd);

    hgemm<true, true, true><<<dim3((2 * Dd) / 128, (Bsz * CTX + 127) / 128, 1), 256, SMEM_NT>>>(
        p_ctx, p_wctxT, bctx, p_kv,
        Bsz * CTX, 2 * Dd, Dd, Dd, Dd, 2 * Dd, 0, 0, 0);

    // ---- join: attention needs q (s2) + kv (main) ----
    cudaStreamWaitEvent(0, e2, 0);

    attn_mma<<<dim3(Bsz * Hh), 128, ATTN_SMEM>>>(p_y);

    hgemm<true, true, false><<<dim3(Dd / 128, (Bsz * Nn + 127) / 128, 1), 256, SMEM_NT>>>(
        p_y, p_woutT, bout, out,
        Bsz * Nn, Dd, Dd, Dd, Dd, Dd, 0, 0, 0);

    cudaEventDestroy(e0);
    cudaEventDestroy(e1);
    cudaEventDestroy(e2);
    cudaEventDestroy(e3);
    cudaStreamDestroy(s2);
}

// round 14
// speedup vs baseline: 1.1414x; 1.1020x over previous
#include <cuda_runtime.h>
#include <cuda_fp16.h>
#include <math.h>
#include <stdint.h>

#define Bsz 64
#define Nn  1029
#define Dd  768
#define Hh  12
#define dh  64
#define Kk  128
#define Rr  5
#define Mm  4
#define Pp  1024          // N - R
#define CTX 133           // R + K
#define NT  17            // query tiles of 64 per (b,h)

// ---------------- scratch (static device globals: allocation-free) ----------
__device__ int    g_idx[Bsz];
__device__ __half g_xh[(size_t)Bsz * Nn * Dd];
__device__ __half g_wqT[Dd * Dd];
__device__ __half g_wctxT[2 * Dd * Dd];
__device__ __half g_woutT[Dd * Dd];
__device__ __half g_qctx[(size_t)Bsz * Kk * Dd];
__device__ __half g_probs[(size_t)Bsz * Kk * Pp];
__device__ __half g_ctx[(size_t)Bsz * CTX * Dd];
__device__ __half g_kv[(size_t)Bsz * CTX * 2 * Dd];
__device__ __half g_q[(size_t)Bsz * Nn * Dd];
__device__ __half g_y[(size_t)Bsz * Nn * Dd];

// ---------------- helpers ----------------------------------------------------
__device__ __forceinline__ uint32_t pk2(float a, float b) {
    __half2 h = __floats2half2_rn(a, b);
    return *reinterpret_cast<uint32_t*>(&h);
}

__device__ __forceinline__ void mma_f16(float* c, const uint32_t* a, const uint32_t* b) {
    asm volatile(
        "mma.sync.aligned.m16n8k16.row.col.f32.f16.f16.f32 "
        "{%0,%1,%2,%3}, {%4,%5,%6,%7}, {%8,%9}, {%0,%1,%2,%3};\n"
        : "+f"(c[0]), "+f"(c[1]), "+f"(c[2]), "+f"(c[3])
        : "r"(a[0]), "r"(a[1]), "r"(a[2]), "r"(a[3]), "r"(b[0]), "r"(b[1]));
}

__device__ __forceinline__ void ldsm4(uint32_t& r0, uint32_t& r1, uint32_t& r2,
                                      uint32_t& r3, uint32_t a) {
    asm volatile("ldmatrix.sync.aligned.m8n8.x4.shared.b16 {%0,%1,%2,%3}, [%4];"
                 : "=r"(r0), "=r"(r1), "=r"(r2), "=r"(r3) : "r"(a));
}
__device__ __forceinline__ void ldsm4t(uint32_t& r0, uint32_t& r1, uint32_t& r2,
                                       uint32_t& r3, uint32_t a) {
    asm volatile("ldmatrix.sync.aligned.m8n8.x4.trans.shared.b16 {%0,%1,%2,%3}, [%4];"
                 : "=r"(r0), "=r"(r1), "=r"(r2), "=r"(r3) : "r"(a));
}

__device__ __forceinline__ void cp16(void* smem_dst, const void* gsrc, unsigned bytes) {
    unsigned saddr = (unsigned)__cvta_generic_to_shared(smem_dst);
    asm volatile("cp.async.cg.shared.global [%0], [%1], 16, %2;\n"
                 :: "r"(saddr), "l"(gsrc), "r"(bytes));
}
__device__ __forceinline__ void cp_commit() { asm volatile("cp.async.commit_group;\n"); }
template<int N> __device__ __forceinline__ void cp_wait() {
    asm volatile("cp.async.wait_group %0;\n" :: "n"(N));
}

// ---------------- conversion kernels ------------------------------------------
__global__ void f2h_kernel(const float4* __restrict__ src, uint2* __restrict__ dst, int n4)
{
    int i = blockIdx.x * blockDim.x + threadIdx.x;
    if (i < n4) {
        float4 v = src[i];
        uint2 o;
        o.x = pk2(v.x, v.y);
        o.y = pk2(v.z, v.w);
        dst[i] = o;
    }
}

__global__ void transpose_h(const float* __restrict__ src, __half* __restrict__ dst,
                            int K, int N)
{
    __shared__ float t[32][33];
    int k0 = blockIdx.y * 32, n0 = blockIdx.x * 32;
    int tx = threadIdx.x, ty = threadIdx.y;   // 32 x 8
    for (int i = ty; i < 32; i += 8)
        t[i][tx] = src[(size_t)(k0 + i) * N + n0 + tx];
    __syncthreads();
    for (int i = ty; i < 32; i += 8)
        dst[(size_t)(n0 + i) * K + k0 + tx] = __float2half_rn(t[tx][i]);
}

// ---------------- cls_n, sims, argmax (fp32 exact) ---------------------------
__global__ void cls_kernel(const float* __restrict__ x,
                           const float* __restrict__ cent,
                           float* __restrict__ cls_out,
                           float* __restrict__ idx_out)
{
    int b = blockIdx.x;
    int tid = threadIdx.x;
    __shared__ float xs[Dd];
    __shared__ float red[256];
    __shared__ float sims[Mm];
    __shared__ float inv_s;

    float ss = 0.f;
    for (int i = tid; i < Dd; i += 256) {
        float v = x[(size_t)b * Nn * Dd + i];
        xs[i] = v;
        ss += v * v;
    }
    red[tid] = ss; __syncthreads();
    for (int s = 128; s > 0; s >>= 1) { if (tid < s) red[tid] += red[tid + s]; __syncthreads(); }
    if (tid == 0) inv_s = 1.f / fmaxf(sqrtf(red[0]), 1e-12f);
    __syncthreads();
    float inv = inv_s;

    for (int m = 0; m < Mm; m++) {
        float p = 0.f;
        for (int i = tid; i < Dd; i += 256) p += xs[i] * cent[m * Dd + i];
        red[tid] = p; __syncthreads();
        for (int s = 128; s > 0; s >>= 1) { if (tid < s) red[tid] += red[tid + s]; __syncthreads(); }
        if (tid == 0) sims[m] = red[0] * inv;
        __syncthreads();
    }
    if (tid == 0) {
        int best = 0; float bv = sims[0];
        for (int m = 1; m < Mm; m++) if (sims[m] > bv) { bv = sims[m]; best = m; }
        g_idx[b] = best;
        if (idx_out) idx_out[b] = (float)best;
    }
    if (cls_out)
        for (int i = tid; i < Dd; i += 256)
            cls_out[(size_t)b * Dd + i] = xs[i] * inv;
}

// ---------------- gather Q_banks[idx] (half, 2-D grid, float4) ---------------
__global__ void gather_qctx_kernel(const float* __restrict__ Qb)
{
    int b = blockIdx.y;
    int i4 = blockIdx.x * blockDim.x + threadIdx.x;
    const int n4 = Kk * Dd / 4;
    if (i4 < n4) {
        const float4 v = reinterpret_cast<const float4*>(
            Qb + (size_t)g_idx[b] * Kk * Dd)[i4];
        uint2 o;
        o.x = pk2(v.x, v.y);
        o.y = pk2(v.z, v.w);
        reinterpret_cast<uint2*>(g_qctx + (size_t)b * Kk * Dd)[i4] = o;
    }
}

__global__ void xreg_kernel()
{
    int i = blockIdx.x * blockDim.x + threadIdx.x;       // u32 units
    const int total = Bsz * Rr * Dd / 2;
    if (i < total) {
        int b = i / (Rr * Dd / 2);
        int r = i - b * (Rr * Dd / 2);
        reinterpret_cast<uint32_t*>(g_ctx)[(size_t)b * CTX * Dd / 2 + r] =
            reinterpret_cast<const uint32_t*>(g_xh)[(size_t)b * Nn * Dd / 2 + r];
    }
}

// ---------------- fp16 tensor-core GEMM: BK=64, 3 stages, ldmatrix ----------
// C[M,N] = A[M,Kd] @ op(B) (+bias). One barrier per 64-k block.
// A / B-NT stage: [128 rows][72-half pitch]. B-NN stage: [64 k][136 halfs].
// Requires Kd % 64 == 0 (768 or 1024 at all call sites); N % 128 == 0.
template<bool TRANSB, bool BIAS, bool OUTHALF>
__global__ __launch_bounds__(256, 2)
void hgemm(const __half* __restrict__ A, const __half* __restrict__ Bm,
           const float* __restrict__ bias, void* __restrict__ Cv,
           int M, int N, int Kd, int lda, int ldb, int ldc,
           long long sA, long long sB, long long sC)
{
    extern __shared__ uint32_t smu[];
    const int ASTG = 128 * 36;                        // u32 per A stage (72-half pitch)
    const int BSTG = TRANSB ? 128 * 36 : 64 * 68;     // NN: [64 k][136 halfs]
    uint32_t* smA = smu;
    uint32_t* smB = smu + 3 * ASTG;
    const uint32_t sbA = (uint32_t)__cvta_generic_to_shared(smA);
    const uint32_t sbB = (uint32_t)__cvta_generic_to_shared(smB);

    const __half* Ab = A  + (long long)blockIdx.z * sA;
    const __half* Bb = Bm + (long long)blockIdx.z * sB;

    const int row0 = blockIdx.y * 128;
    const int col0 = blockIdx.x * 128;
    const int tid  = threadIdx.x;
    const int lane = tid & 31;
    const int warp = tid >> 5;
    const int wm = warp >> 1;
    const int wn = warp & 1;
    const int g   = lane >> 2;
    const int tig = lane & 3;

    const int lrow = ((lane >> 3) & 1) * 8 + (lane & 7);
    const int lk8  = (lane >> 4) * 8;
    uint32_t aoff[2], boff[4];
#pragma unroll
    for (int im = 0; im < 2; im++)
        aoff[im] = (uint32_t)(((wm * 32 + im * 16 + lrow) * 72 + lk8) * 2);
#pragma unroll
    for (int p = 0; p < 4; p++) {
        if (TRANSB)
            boff[p] = (uint32_t)(((wn * 64 + p * 16 + lrow) * 72 + lk8) * 2);
        else
            boff[p] = (uint32_t)(((((lane >> 4) & 1) * 8 + (lane & 7)) * 136
                                  + wn * 64 + p * 16 + ((lane >> 3) & 1) * 8) * 2);
    }

    float acc[2][8][4];
#pragma unroll
    for (int im = 0; im < 2; im++)
#pragma unroll
        for (int in = 0; in < 8; in++)
#pragma unroll
            for (int j = 0; j < 4; j++) acc[im][in][j] = 0.f;

    auto loadA = [&](int stg, int k0) {
        uint32_t* dst = smA + stg * ASTG;
#pragma unroll
        for (int it = 0; it < 4; it++) {
            int id = tid + it * 256;              // 0..1023
            int r  = id >> 3;                     // 0..127
            int ch = id & 7;                      // 8 x 16B chunks (64 halfs/row)
            int gr = row0 + r;
            unsigned ok = (gr < M) ? 16u : 0u;
            const __half* src = Ab + (size_t)(gr < M ? gr : 0) * lda + k0 + ch * 8;
            cp16(dst + r * 36 + ch * 4, src, ok);
        }
    };
    auto loadB = [&](int stg, int k0) {
        uint32_t* dst = smB + stg * BSTG;
#pragma unroll
        for (int it = 0; it < 4; it++) {
            int id = tid + it * 256;              // 0..1023
            if (TRANSB) {
                int n  = id >> 3;
                int ch = id & 7;
                cp16(dst + n * 36 + ch * 4, Bb + (size_t)(col0 + n) * ldb + k0 + ch * 8, 16u);
            } else {
                int kr = id >> 4;                 // 0..63
                int ch = id & 15;                 // 16 x 16B chunks (128 halfs/row)
                cp16(dst + kr * 68 + ch * 4, Bb + (size_t)(k0 + kr) * ldb + col0 + ch * 8, 16u);
            }
        }
    };

    const int nk = Kd >> 6;                       // 64-k blocks (12 or 16)
    loadA(0, 0);  loadB(0, 0);  cp_commit();
    loadA(1, 64); loadB(1, 64); cp_commit();

    for (int i = 0; i < nk; i++) {
        if (i + 1 < nk) cp_wait<1>(); else cp_wait<0>();
        __syncthreads();
        if (i + 2 < nk) {
            int s3 = (i + 2) % 3;
            loadA(s3, (i + 2) * 64);
            loadB(s3, (i + 2) * 64);
            cp_commit();
        }

        const uint32_t baA = sbA + (uint32_t)((i % 3) * ASTG * 4);
        const uint32_t baB = sbB + (uint32_t)((i % 3) * BSTG * 4);

#pragma unroll
        for (int s = 0; s < 4; s++) {             // four k16 steps per 64-k block
            uint32_t afr[2][4], bfr[8][2];
#pragma unroll
            for (int im = 0; im < 2; im++)
                ldsm4(afr[im][0], afr[im][1], afr[im][2], afr[im][3],
                      baA + aoff[im] + s * 32);
#pragma unroll
            for (int p = 0; p < 4; p++) {
                if (TRANSB)
                    ldsm4(bfr[2 * p][0], bfr[2 * p + 1][0], bfr[2 * p][1], bfr[2 * p + 1][1],
                          baB + boff[p] + s * 32);
                else
                    ldsm4t(bfr[2 * p][0], bfr[2 * p + 1][0], bfr[2 * p][1], bfr[2 * p + 1][1],
                           baB + boff[p] + s * 4352);
            }
#pragma unroll
            for (int im = 0; im < 2; im++)
#pragma unroll
                for (int in = 0; in < 8; in++)
                    mma_f16(acc[im][in], afr[im], bfr[in]);
        }
        // trailing barrier elided: writes at iter i target stage (i+2)%3 whose
        // last readers (iter i-1) passed this iteration's leading barrier.
    }

#pragma unroll
    for (int im = 0; im < 2; im++) {
        int rb = row0 + wm * 32 + im * 16 + g;
#pragma unroll
        for (int in = 0; in < 8; in++) {
            int cb = col0 + wn * 64 + in * 8 + 2 * tig;
            float b0 = BIAS ? bias[cb] : 0.f;
            float b1 = BIAS ? bias[cb + 1] : 0.f;
            float v0 = acc[im][in][0] + b0, v1 = acc[im][in][1] + b1;
            float v2 = acc[im][in][2] + b0, v3 = acc[im][in][3] + b1;
            if (OUTHALF) {
                __half* C = (__half*)Cv + (long long)blockIdx.z * sC;
                if (rb < M)
                    *reinterpret_cast<uint32_t*>(&C[(size_t)rb * ldc + cb]) = pk2(v0, v1);
                if (rb + 8 < M)
                    *reinterpret_cast<uint32_t*>(&C[(size_t)(rb + 8) * ldc + cb]) = pk2(v2, v3);
            } else {
                float* C = (float*)Cv + (long long)blockIdx.z * sC;
                if (rb < M)
                    *reinterpret_cast<float2*>(&C[(size_t)rb * ldc + cb]) = make_float2(v0, v1);
                if (rb + 8 < M)
                    *reinterpret_cast<float2*>(&C[(size_t)(rb + 8) * ldc + cb]) = make_float2(v2, v3);
            }
        }
    }
}

// ---------------- row softmax over P=1024: half in-place ----------------------
__global__ void softmax_kernel(__half* __restrict__ pr)
{
    int row = blockIdx.x;
    uint2* p2 = reinterpret_cast<uint2*>(pr + (size_t)row * Pp);
    int tid = threadIdx.x;
    __shared__ float red[256];

    uint2 u = p2[tid];
    __half2 h0 = *reinterpret_cast<__half2*>(&u.x);
    __half2 h1 = *reinterpret_cast<__half2*>(&u.y);
    float vx = __low2float(h0), vy = __high2float(h0);
    float vz = __low2float(h1), vw = __high2float(h1);

    float mx = fmaxf(fmaxf(vx, vy), fmaxf(vz, vw));
    red[tid] = mx; __syncthreads();
    for (int st = 128; st > 0; st >>= 1) { if (tid < st) red[tid] = fmaxf(red[tid], red[tid + st]); __syncthreads(); }
    mx = red[0]; __syncthreads();

    vx = __expf(vx - mx); vy = __expf(vy - mx);
    vz = __expf(vz - mx); vw = __expf(vw - mx);
    float sm = vx + vy + vz + vw;
    red[tid] = sm; __syncthreads();
    for (int st = 128; st > 0; st >>= 1) { if (tid < st) red[tid] += red[tid + st]; __syncthreads(); }
    float inv = 1.f / red[0];
    uint2 o;
    o.x = pk2(vx * inv, vy * inv);
    o.y = pk2(vz * inv, vw * inv);
    p2[tid] = o;
}

// ---------------- fp16 fused attention: persistent per (b,h) ------------------
__global__ __launch_bounds__(128, 3)
void attn_mma(__half* __restrict__ y)
{
    extern __shared__ uint32_t smu[];
    uint32_t* Qs = smu;                    // [64][36] u32  (72-half pitch)
    uint32_t* Ks = smu + 64 * 36;          // [144][36]
    uint32_t* Vs = Ks + 144 * 36;          // [144][36]
    uint32_t* Ps = Vs + 144 * 36;          // [64][76] u32  (152-half pitch)
    const uint32_t sQ = (uint32_t)__cvta_generic_to_shared(Qs);
    const uint32_t sK = (uint32_t)__cvta_generic_to_shared(Ks);
    const uint32_t sV = (uint32_t)__cvta_generic_to_shared(Vs);
    const uint32_t sP = (uint32_t)__cvta_generic_to_shared(Ps);

    const int bh = blockIdx.x;
    const int b = bh / Hh, h = bh % Hh;
    const int tid = threadIdx.x;
    const int lane = tid & 31;
    const int w = tid >> 5;                // 0..3
    const int g = lane >> 2;
    const int tig = lane & 3;
    const int rbase = w * 16;

    const int lrow = ((lane >> 3) & 1) * 8 + (lane & 7);
    const int lk8  = (lane >> 4) * 8;

    const __half* qbase = g_q + (size_t)b * Nn * Dd + h * dh;

    auto loadQ = [&](int n0) {
#pragma unroll
        for (int it = 0; it < 4; it++) {
            int id = tid + it * 128;       // 0..511
            int r  = id >> 3;              // 0..63
            int ch = id & 7;
            int n  = n0 + r;
            unsigned ok = (n < Nn) ? 16u : 0u;
            cp16(Qs + r * 36 + ch * 4, qbase + (size_t)(n < Nn ? n : 0) * Dd + ch * 8, ok);
        }
    };

    // ---- K and V tiles 144x64 halfs, loaded once -------------------------------
#pragma unroll
    for (int it = 0; it < 18; it++) {
        int id = tid + it * 128;           // 0..2303
        int half = id & 1;                 // 0 = K, 1 = V
        int key  = (id >> 1) >> 3;         // 0..143
        int ch   = (id >> 1) & 7;
        unsigned ok = (key < CTX) ? 16u : 0u;
        const __half* src = g_kv + ((size_t)b * CTX + (key < CTX ? key : 0)) * (2 * Dd)
                          + half * Dd + h * dh + ch * 8;
        uint32_t* dst = (half ? Vs : Ks) + key * 36 + ch * 4;
        cp16(dst, src, ok);
    }
    loadQ(0);
    cp_commit();

    const uint32_t koff  = sK + (uint32_t)((lrow * 72 + lk8) * 2);
    const uint32_t qoff  = sQ + (uint32_t)(((rbase + lrow) * 72 + lk8) * 2);
    const uint32_t poff  = sP + (uint32_t)(((rbase + lrow) * 152 + lk8) * 2);
    const uint32_t voff  = sV + (uint32_t)(((((lane >> 4) & 1) * 8 + (lane & 7)) * 72
                                            + ((lane >> 3) & 1) * 8) * 2);
    const float scale = 0.125f;

    for (int t = 0; t < NT; t++) {
        const int n0 = t * 64;
        cp_wait<0>();
        __syncthreads();                   // Q tile t visible to all

        uint32_t afr[4][4];
#pragma unroll
        for (int ks = 0; ks < 4; ks++)
            ldsm4(afr[ks][0], afr[ks][1], afr[ks][2], afr[ks][3],
                  qoff + (uint32_t)(ks * 32));
        __syncthreads();
        if (t + 1 < NT) { loadQ(n0 + 64); cp_commit(); }

        // ---- phase 1: S = Q K^T -------------------------------------------------
        float sacc[18][4];
#pragma unroll
        for (int nt = 0; nt < 18; nt++)
#pragma unroll
            for (int j = 0; j < 4; j++) sacc[nt][j] = 0.f;

#pragma unroll
        for (int ntp = 0; ntp < 9; ntp++) {
#pragma unroll
            for (int ks = 0; ks < 4; ks++) {
                uint32_t bfr[2][2];
                ldsm4(bfr[0][0], bfr[1][0], bfr[0][1], bfr[1][1],
                      koff + (uint32_t)(ntp * 2304 + ks * 32));
                mma_f16(sacc[2 * ntp],     afr[ks], bfr[0]);
                mma_f16(sacc[2 * ntp + 1], afr[ks], bfr[1]);
            }
        }

        // ---- exact softmax over 133 keys ---------------------------------------
        float mlo = -1e30f, mhi = -1e30f;
#pragma unroll
        for (int nt = 0; nt < 18; nt++) {
            int c0 = nt * 8 + 2 * tig;
            float s0 = (c0     < CTX) ? sacc[nt][0] * scale : -1e30f;
            float s1 = (c0 + 1 < CTX) ? sacc[nt][1] * scale : -1e30f;
            float s2 = (c0     < CTX) ? sacc[nt][2] * scale : -1e30f;
            float s3 = (c0 + 1 < CTX) ? sacc[nt][3] * scale : -1e30f;
            sacc[nt][0] = s0; sacc[nt][1] = s1; sacc[nt][2] = s2; sacc[nt][3] = s3;
            mlo = fmaxf(mlo, fmaxf(s0, s1));
            mhi = fmaxf(mhi, fmaxf(s2, s3));
        }
        mlo = fmaxf(mlo, __shfl_xor_sync(0xffffffffu, mlo, 1));
        mlo = fmaxf(mlo, __shfl_xor_sync(0xffffffffu, mlo, 2));
        mhi = fmaxf(mhi, __shfl_xor_sync(0xffffffffu, mhi, 1));
        mhi = fmaxf(mhi, __shfl_xor_sync(0xffffffffu, mhi, 2));

        float llo = 0.f, lhi = 0.f;
#pragma unroll
        for (int nt = 0; nt < 18; nt++) {
            float p0 = __expf(sacc[nt][0] - mlo);
            float p1 = __expf(sacc[nt][1] - mlo);
            float p2 = __expf(sacc[nt][2] - mhi);
            float p3 = __expf(sacc[nt][3] - mhi);
            llo += p0 + p1; lhi += p2 + p3;
            sacc[nt][0] = p0; sacc[nt][1] = p1; sacc[nt][2] = p2; sacc[nt][3] = p3;
        }
        llo += __shfl_xor_sync(0xffffffffu, llo, 1);
        llo += __shfl_xor_sync(0xffffffffu, llo, 2);
        lhi += __shfl_xor_sync(0xffffffffu, lhi, 1);
        lhi += __shfl_xor_sync(0xffffffffu, lhi, 2);

        // ---- P -> smem (per-warp rows only) ------------------------------------
#pragma unroll
        for (int nt = 0; nt < 18; nt++) {
            Ps[(rbase + g) * 76 + nt * 4 + tig]     = pk2(sacc[nt][0], sacc[nt][1]);
            Ps[(rbase + g + 8) * 76 + nt * 4 + tig] = pk2(sacc[nt][2], sacc[nt][3]);
        }
        __syncwarp();

        // ---- phase 2: O = P V ---------------------------------------------------
        float oacc[8][4];
#pragma unroll
        for (int nt = 0; nt < 8; nt++)
#pragma unroll
            for (int j = 0; j < 4; j++) oacc[nt][j] = 0.f;

#pragma unroll
        for (int ks = 0; ks < 9; ks++) {
            uint32_t a2[4];
            ldsm4(a2[0], a2[1], a2[2], a2[3], poff + (uint32_t)(ks * 32));
#pragma unroll
            for (int ntp = 0; ntp < 4; ntp++) {
                uint32_t bfr[2][2];
                ldsm4t(bfr[0][0], bfr[1][0], bfr[0][1], bfr[1][1],
                       voff + (uint32_t)(ks * 2304 + ntp * 32));
                mma_f16(oacc[2 * ntp],     a2, bfr[0]);
                mma_f16(oacc[2 * ntp + 1], a2, bfr[1]);
            }
        }

        // ---- stage O into Ps (own rows) then coalesced 16B row stores -----------
        float invlo = 1.f / llo, invhi = 1.f / lhi;
        __syncwarp();                      // phase-2 reads of Ps rows done
#pragma unroll
        for (int nt = 0; nt < 8; nt++) {
            Ps[(rbase + g) * 76 + nt * 4 + tig]     = pk2(oacc[nt][0] * invlo, oacc[nt][1] * invlo);
            Ps[(rbase + g + 8) * 76 + nt * 4 + tig] = pk2(oacc[nt][2] * invhi, oacc[nt][3] * invhi);
        }
        __syncwarp();
#pragma unroll
        for (int it = 0; it < 4; it++) {
            int id = lane + it * 32;       // 0..127
            int r  = id >> 3;              // 0..15 (own warp's rows)
            int ch = id & 7;               // 16B chunk
            int n  = n0 + rbase + r;
            if (n < Nn) {
                uint4 v = *reinterpret_cast<const uint4*>(&Ps[(rbase + r) * 76 + ch * 4]);
                *reinterpret_cast<uint4*>(&y[((size_t)b * Nn + n) * Dd + h * dh + ch * 8]) = v;
            }
        }
    }
}

// ---------------- launch -----------------------------------------------------
extern "C" void kernel_launch(void* const* d_in, const int* in_sizes, int n_in,
                              void* d_out, int out_size)
{
    const float* x    = (const float*)d_in[0];
    const float* Qb   = (const float*)d_in[1];
    const float* Wq   = (const float*)d_in[2];
    const float* Wctx = (const float*)d_in[3];
    const float* bctx = (const float*)d_in[4];
    const float* Wout = (const float*)d_in[5];
    const float* bout = (const float*)d_in[6];
    const float* cent = (const float*)d_in[7];
    float* out = (float*)d_out;

    __half *p_xh, *p_wqT, *p_wctxT, *p_woutT, *p_qctx, *p_probs, *p_ctx, *p_kv, *p_q, *p_y;
    cudaGetSymbolAddress((void**)&p_xh,     g_xh);
    cudaGetSymbolAddress((void**)&p_wqT,    g_wqT);
    cudaGetSymbolAddress((void**)&p_wctxT,  g_wctxT);
    cudaGetSymbolAddress((void**)&p_woutT,  g_woutT);
    cudaGetSymbolAddress((void**)&p_qctx,   g_qctx);
    cudaGetSymbolAddress((void**)&p_probs,  g_probs);
    cudaGetSymbolAddress((void**)&p_ctx,    g_ctx);
    cudaGetSymbolAddress((void**)&p_kv,     g_kv);
    cudaGetSymbolAddress((void**)&p_q,      g_q);
    cudaGetSymbolAddress((void**)&p_y,      g_y);

    const int SMEM_NT  = (3 * 128 * 36 + 3 * 128 * 36) * 4;   // 110592
    const int SMEM_NN  = (3 * 128 * 36 + 3 * 64 * 68) * 4;    // 107520
    const int ATTN_SMEM = (64 * 36 + 144 * 36 + 144 * 36 + 64 * 76) * 4;  // 70144
    cudaFuncSetAttribute((const void*)hgemm<true,  false, true >, cudaFuncAttributeMaxDynamicSharedMemorySize, SMEM_NT);
    cudaFuncSetAttribute((const void*)hgemm<true,  true,  true >, cudaFuncAttributeMaxDynamicSharedMemorySize, SMEM_NT);
    cudaFuncSetAttribute((const void*)hgemm<true,  true,  false>, cudaFuncAttributeMaxDynamicSharedMemorySize, SMEM_NT);
    cudaFuncSetAttribute((const void*)hgemm<false, false, true >, cudaFuncAttributeMaxDynamicSharedMemorySize, SMEM_NN);
    cudaFuncSetAttribute((const void*)attn_mma, cudaFuncAttributeMaxDynamicSharedMemorySize, ATTN_SMEM);

    const size_t main_sz = (size_t)Bsz * Nn * Dd;
    float* cls_out = nullptr;
    float* idx_out = nullptr;
    if ((size_t)out_size >= main_sz + (size_t)Bsz * Dd + Bsz) {
        cls_out = out + main_sz;
        idx_out = out + main_sz + (size_t)Bsz * Dd;
    }

    cudaStream_t s2;
    cudaStreamCreateWithFlags(&s2, cudaStreamNonBlocking);
    cudaEvent_t e0, e1, e2, e3;
    cudaEventCreateWithFlags(&e0, cudaEventDisableTiming);
    cudaEventCreateWithFlags(&e1, cudaEventDisableTiming);
    cudaEventCreateWithFlags(&e2, cudaEventDisableTiming);
    cudaEventCreateWithFlags(&e3, cudaEventDisableTiming);

    // ---- legal capture fork: record on capturing stream FIRST ----
    cudaEventRecord(e0, 0);
    cudaStreamWaitEvent(s2, e0, 0);

    // main: convert x -> half
    {
        int n4 = (int)(main_sz / 4);
        f2h_kernel<<<(n4 + 255) / 256, 256>>>((const float4*)x, (uint2*)p_xh, n4);
    }
    cudaEventRecord(e1, 0);

    // ---- side chain (s2): f2h-independent prologue, then q GEMM ----
    transpose_h<<<dim3(Dd / 32, Dd / 32), dim3(32, 8), 0, s2>>>(Wq, p_wqT, Dd, Dd);
    cls_kernel<<<Bsz, 256, 0, s2>>>(x, cent, cls_out, idx_out);
    gather_qctx_kernel<<<dim3(Kk * Dd / 4 / 256, Bsz), 256, 0, s2>>>(Qb);
    cudaEventRecord(e3, s2);                  // qctx ready
    cudaStreamWaitEvent(s2, e1, 0);           // need xh for q GEMM
    hgemm<true, false, true><<<dim3(Dd / 128, (Bsz * Nn + 127) / 128, 1), 256, SMEM_NT, s2>>>(
        p_xh, p_wqT, nullptr, p_q,
        Bsz * Nn, Dd, Dd, Dd, Dd, Dd, 0, 0, 0);
    cudaEventRecord(e2, s2);

    // ---- main chain: ctx pipeline ----
    transpose_h<<<dim3(2 * Dd / 32, Dd / 32), dim3(32, 8)>>>(Wctx, p_wctxT, Dd, 2 * Dd);
    transpose_h<<<dim3(Dd / 32, Dd / 32), dim3(32, 8)>>>(Wout, p_woutT, Dd, Dd);
    xreg_kernel<<<(Bsz * Rr * Dd / 2 + 255) / 256, 256>>>();

    cudaStreamWaitEvent(0, e3, 0);            // need qctx

    hgemm<true, false, true><<<dim3(Pp / 128, 1, Bsz), 256, SMEM_NT>>>(
        p_qctx, p_xh + (size_t)Rr * Dd, nullptr, p_probs,
        Kk, Pp, Dd, Dd, Dd, Pp,
        (long long)Kk * Dd, (long long)Nn * Dd, (long long)Kk * Pp);

    softmax_kernel<<<Bsz * Kk, 256>>>(p_probs);

    hgemm<false, false, true><<<dim3(Dd / 128, 1, Bsz), 256, SMEM_NN>>>(
        p_probs, p_xh + (size_t)Rr * Dd, nullptr, p_ctx + (size_t)Rr * Dd,
        Kk, Dd, Pp, Pp, Dd, Dd,
        (long long)Kk * Pp, (long long)Nn * Dd, (long long)CTX * Dd);

    hgemm<true, true, true><<<dim3((2 * Dd) / 128, (Bsz * CTX + 127) / 128, 1), 256, SMEM_NT>>>(
        p_ctx, p_wctxT, bctx, p_kv,
        Bsz * CTX, 2 * Dd, Dd, Dd, Dd, 2 * Dd, 0, 0, 0);

    // ---- join: attention needs q (s2) + kv (main) ----
    cudaStreamWaitEvent(0, e2, 0);

    attn_mma<<<dim3(Bsz * Hh), 128, ATTN_SMEM>>>(p_y);

    hgemm<true, true, false><<<dim3(Dd / 128, (Bsz * Nn + 127) / 128, 1), 256, SMEM_NT>>>(
        p_y, p_woutT, bout, out,
        Bsz * Nn, Dd, Dd, Dd, Dd, Dd, 0, 0, 0);

    cudaEventDestroy(e0);
    cudaEventDestroy(e1);
    cudaEventDestroy(e2);
    cudaEventDestroy(e3);
    cudaStreamDestroy(s2);
}